// round 6
// baseline (speedup 1.0000x reference)
#include <cuda_runtime.h>
#include <cstdint>

#define N_USER   150000
#define M_ITEM   30000
#define N_NODES  180000
#define DIM      64
#define BATCH    1024
#define AUX_LD   10246
#define XCOLS    640

// ---------------- scratch (static device memory; no allocs allowed) --------
__device__ float g_embA[(size_t)N_NODES * DIM];
__device__ float g_embB[(size_t)N_NODES * DIM];
__device__ float g_acc [(size_t)N_NODES * DIM];
__device__ float g_X   [BATCH * XCOLS];
__device__ float g_H1  [BATCH * DIM];
__device__ float g_H2  [BATCH * DIM];
__device__ float g_sums[BATCH * 3];

// vectorized no-return global float4 reduction (sm_90+)
__device__ __forceinline__ void red_add_v4(float* p, float4 v) {
    asm volatile("red.global.add.v4.f32 [%0], {%1,%2,%3,%4};"
                 :: "l"(p), "f"(v.x), "f"(v.y), "f"(v.z), "f"(v.w) : "memory");
}

// ---------------- LightGCN ------------------------------------------------
// emb0 = concat(user_rel, item_rel); acc = emb0
__global__ void init_emb_kernel(const float* __restrict__ user_rel,
                                const float* __restrict__ item_rel,
                                float* __restrict__ emb, float* __restrict__ acc) {
    size_t idx = (size_t)blockIdx.x * blockDim.x + threadIdx.x;   // float4 index
    const size_t US4 = (size_t)N_USER * DIM / 4;                  // 2.4M
    const size_t TOT4 = (size_t)N_NODES * DIM / 4;                // 2.88M
    if (idx >= TOT4) return;
    float4 v = (idx < US4) ? reinterpret_cast<const float4*>(user_rel)[idx]
                           : reinterpret_cast<const float4*>(item_rel)[idx - US4];
    reinterpret_cast<float4*>(emb)[idx] = v;
    reinterpret_cast<float4*>(acc)[idx] = v;
}

// dst[row] += val * src[col]   (16 threads per edge, float4 each)
__global__ void spmm_kernel(const float* __restrict__ src, float* __restrict__ dst,
                            const int* __restrict__ row, const int* __restrict__ col,
                            const float* __restrict__ val, int nnz) {
    long gid = (long)blockIdx.x * blockDim.x + threadIdx.x;
    int e = (int)(gid >> 4);
    int q = (int)(gid & 15);
    if (e >= nnz) return;
    int r = __ldg(row + e);
    int c = __ldg(col + e);
    float v = __ldg(val + e);
    float4 x = *reinterpret_cast<const float4*>(src + (size_t)c * DIM + q * 4);
    float4 y = make_float4(v * x.x, v * x.y, v * x.z, v * x.w);
    red_add_v4(dst + (size_t)r * DIM + q * 4, y);
}

__global__ void acc_add_kernel(float* __restrict__ acc, const float* __restrict__ e) {
    size_t idx = (size_t)blockIdx.x * blockDim.x + threadIdx.x;
    const size_t TOT4 = (size_t)N_NODES * DIM / 4;
    if (idx >= TOT4) return;
    float4 a = reinterpret_cast<float4*>(acc)[idx];
    float4 b = reinterpret_cast<const float4*>(e)[idx];
    a.x += b.x; a.y += b.y; a.z += b.z; a.w += b.w;
    reinterpret_cast<float4*>(acc)[idx] = a;
}

// ---------------- multi-hot row sums --------------------------------------
__global__ void rowsums_kernel(const int* __restrict__ aux, float* __restrict__ sums) {
    int b = blockIdx.x;
    int t = threadIdx.x;
    const int* a = aux + (size_t)b * AUX_LD;
    float s0 = 0.f, s1 = 0.f, s2 = 0.f;
    for (int j = 1 + t;    j < 26;    j += 256) s0 += (float)a[j];
    for (int j = 26 + t;   j < 2212;  j += 256) s1 += (float)a[j];
    for (int j = 2212 + t; j < 10242; j += 256) s2 += (float)a[j];
    __shared__ float sd0[256], sd1[256], sd2[256];
    sd0[t] = s0; sd1[t] = s1; sd2[t] = s2;
    __syncthreads();
    for (int off = 128; off > 0; off >>= 1) {
        if (t < off) { sd0[t] += sd0[t + off]; sd1[t] += sd1[t + off]; sd2[t] += sd2[t + off]; }
        __syncthreads();
    }
    if (t == 0) {
        sums[b * 3 + 0] = sd0[0];
        sums[b * 3 + 1] = sd1[0];
        sums[b * 3 + 2] = sd2[0];
    }
}

// ---------------- multi-hot GEMM: X[:,colOut:colOut+64] += (x@W)/rowsum ----
// 64-row x 64-col tile per block, K-split over blockIdx.y, atomic partials.
__global__ __launch_bounds__(256)
void mh_gemm_kernel(const int* __restrict__ aux, int colIn, int K, int tilesPerBlock,
                    const float* __restrict__ W,
                    const float* __restrict__ sums, int sumIdx,
                    float* __restrict__ X, int colOut) {
    __shared__ float xs[64][33];
    __shared__ float ws[32][64];
    int t  = threadIdx.x;
    int tx = t & 15;         // 4 output cols: 4*tx..4*tx+3
    int ty = t >> 4;         // 4 output rows: 4*ty..4*ty+3
    int rowBase = blockIdx.x * 64;
    int kStart = blockIdx.y * tilesPerBlock * 32;
    int kEnd   = min(K, kStart + tilesPerBlock * 32);

    float acc[4][4] = {};
    for (int k0 = kStart; k0 < kEnd; k0 += 32) {
        // load A tile (coalesced in k); 2048 elems / 256 thr = 8 each
        #pragma unroll
        for (int i = 0; i < 8; i++) {
            int l = t + 256 * i;
            int kk = l & 31, rr = l >> 5;
            int kg = k0 + kk;
            xs[rr][kk] = (kg < K) ? (float)aux[(size_t)(rowBase + rr) * AUX_LD + colIn + kg] : 0.f;
        }
        // load W tile (coalesced)
        #pragma unroll
        for (int i = 0; i < 8; i++) {
            int l = t + 256 * i;
            int cc = l & 63, kk = l >> 6;
            int kg = k0 + kk;
            ws[kk][cc] = (kg < K) ? W[(size_t)kg * 64 + cc] : 0.f;
        }
        __syncthreads();
        #pragma unroll
        for (int k = 0; k < 32; k++) {
            float4 wv = *reinterpret_cast<float4*>(&ws[k][tx * 4]);
            float a0 = xs[ty * 4 + 0][k];
            float a1 = xs[ty * 4 + 1][k];
            float a2 = xs[ty * 4 + 2][k];
            float a3 = xs[ty * 4 + 3][k];
            acc[0][0] += a0 * wv.x; acc[0][1] += a0 * wv.y; acc[0][2] += a0 * wv.z; acc[0][3] += a0 * wv.w;
            acc[1][0] += a1 * wv.x; acc[1][1] += a1 * wv.y; acc[1][2] += a1 * wv.z; acc[1][3] += a1 * wv.w;
            acc[2][0] += a2 * wv.x; acc[2][1] += a2 * wv.y; acc[2][2] += a2 * wv.z; acc[2][3] += a2 * wv.w;
            acc[3][0] += a3 * wv.x; acc[3][1] += a3 * wv.y; acc[3][2] += a3 * wv.z; acc[3][3] += a3 * wv.w;
        }
        __syncthreads();
    }
    #pragma unroll
    for (int r = 0; r < 4; r++) {
        int row = rowBase + ty * 4 + r;
        float rn = 1.0f / sums[row * 3 + sumIdx];
        float4 v = make_float4(acc[r][0] * rn, acc[r][1] * rn, acc[r][2] * rn, acc[r][3] * rn);
        red_add_v4(&X[(size_t)row * XCOLS + colOut + tx * 4], v);
    }
}

// ---------------- dense GEMM (partial sums into pre-zeroed out) -----------
__global__ __launch_bounds__(256)
void fc_gemm_kernel(const float* __restrict__ A, int lda, int K, int tilesPerBlock,
                    const float* __restrict__ W, float* __restrict__ out, int ldo) {
    __shared__ float xs[64][33];
    __shared__ float ws[32][64];
    int t  = threadIdx.x;
    int tx = t & 15;
    int ty = t >> 4;
    int rowBase = blockIdx.x * 64;
    int kStart = blockIdx.y * tilesPerBlock * 32;
    int kEnd   = min(K, kStart + tilesPerBlock * 32);

    float acc[4][4] = {};
    for (int k0 = kStart; k0 < kEnd; k0 += 32) {
        #pragma unroll
        for (int i = 0; i < 8; i++) {
            int l = t + 256 * i;
            int kk = l & 31, rr = l >> 5;
            int kg = k0 + kk;
            xs[rr][kk] = (kg < K) ? A[(size_t)(rowBase + rr) * lda + kg] : 0.f;
        }
        #pragma unroll
        for (int i = 0; i < 8; i++) {
            int l = t + 256 * i;
            int cc = l & 63, kk = l >> 6;
            int kg = k0 + kk;
            ws[kk][cc] = (kg < K) ? W[(size_t)kg * 64 + cc] : 0.f;
        }
        __syncthreads();
        #pragma unroll
        for (int k = 0; k < 32; k++) {
            float4 wv = *reinterpret_cast<float4*>(&ws[k][tx * 4]);
            float a0 = xs[ty * 4 + 0][k];
            float a1 = xs[ty * 4 + 1][k];
            float a2 = xs[ty * 4 + 2][k];
            float a3 = xs[ty * 4 + 3][k];
            acc[0][0] += a0 * wv.x; acc[0][1] += a0 * wv.y; acc[0][2] += a0 * wv.z; acc[0][3] += a0 * wv.w;
            acc[1][0] += a1 * wv.x; acc[1][1] += a1 * wv.y; acc[1][2] += a1 * wv.z; acc[1][3] += a1 * wv.w;
            acc[2][0] += a2 * wv.x; acc[2][1] += a2 * wv.y; acc[2][2] += a2 * wv.z; acc[2][3] += a2 * wv.w;
            acc[3][0] += a3 * wv.x; acc[3][1] += a3 * wv.y; acc[3][2] += a3 * wv.z; acc[3][3] += a3 * wv.w;
        }
        __syncthreads();
    }
    #pragma unroll
    for (int r = 0; r < 4; r++) {
        int row = rowBase + ty * 4 + r;
        float4 v = make_float4(acc[r][0], acc[r][1], acc[r][2], acc[r][3]);
        red_add_v4(&out[(size_t)row * ldo + tx * 4], v);
    }
}

__global__ void bias_act_kernel(float* __restrict__ h, const float* __restrict__ b, int n) {
    int i = blockIdx.x * blockDim.x + threadIdx.x;
    if (i >= n) return;
    float v = h[i] + b[i & 63];
    h[i] = v > 0.f ? v : 0.f;
}

// ---------------- single-index gathers + GCN gather into X ----------------
__global__ void gather_kernel(const int* __restrict__ aux,
                              const int* __restrict__ uid, const int* __restrict__ iid,
                              const float* __restrict__ rate_tab,
                              const float* __restrict__ gender_tab,
                              const float* __restrict__ age_tab,
                              const float* __restrict__ occ_tab,
                              const float* __restrict__ area_tab,
                              const float* __restrict__ acc, float* __restrict__ X) {
    int b = blockIdx.x;
    int d = threadIdx.x;   // 64
    const int* a = aux + (size_t)b * AUX_LD;
    float* xr = X + (size_t)b * XCOLS;
    xr[0   + d] = rate_tab  [(size_t)a[0]     * 64 + d];
    xr[256 + d] = gender_tab[(size_t)a[10242] * 64 + d];
    xr[320 + d] = age_tab   [(size_t)a[10243] * 64 + d];
    xr[384 + d] = occ_tab   [(size_t)a[10244] * 64 + d];
    xr[448 + d] = area_tab  [(size_t)a[10245] * 64 + d];
    int u  = uid[b];
    int it = iid[b];
    xr[512 + d] = 0.25f * acc[(size_t)u * 64 + d];
    xr[576 + d] = 0.25f * acc[((size_t)N_USER + it) * 64 + d];
}

// ---------------- final dot -----------------------------------------------
__global__ void out_kernel(const float* __restrict__ H2, const float* __restrict__ w,
                           const float* __restrict__ ob, float* __restrict__ out) {
    int b = blockIdx.x;
    int t = threadIdx.x;   // 64
    __shared__ float s[64];
    s[t] = H2[(size_t)b * 64 + t] * w[t];
    __syncthreads();
    for (int off = 32; off > 0; off >>= 1) {
        if (t < off) s[t] += s[t + off];
        __syncthreads();
    }
    if (t == 0) out[b] = s[0] + ob[0];
}

// ---------------- launch ---------------------------------------------------
extern "C" void kernel_launch(void* const* d_in, const int* in_sizes, int n_in,
                              void* d_out, int out_size) {
    const int*   aux       = (const int*)  d_in[0];
    const int*   user_ids  = (const int*)  d_in[1];
    const int*   item_ids  = (const int*)  d_in[2];
    const int*   grow      = (const int*)  d_in[3];
    const int*   gcol      = (const int*)  d_in[4];
    const float* gval      = (const float*)d_in[5];
    const float* rate_tab  = (const float*)d_in[6];
    const float* genre_W   = (const float*)d_in[7];
    const float* director_W= (const float*)d_in[8];
    const float* actor_W   = (const float*)d_in[9];
    const float* gender_tab= (const float*)d_in[10];
    const float* age_tab   = (const float*)d_in[11];
    const float* occ_tab   = (const float*)d_in[12];
    const float* area_tab  = (const float*)d_in[13];
    const float* user_rel  = (const float*)d_in[14];
    const float* item_rel  = (const float*)d_in[15];
    const float* fc1_W     = (const float*)d_in[16];
    const float* fc1_b     = (const float*)d_in[17];
    const float* fc2_W     = (const float*)d_in[18];
    const float* fc2_b     = (const float*)d_in[19];
    const float* out_W     = (const float*)d_in[20];
    const float* out_b     = (const float*)d_in[21];
    int nnz = in_sizes[3];

    float *embA, *embB, *acc, *X, *H1, *H2, *sums;
    cudaGetSymbolAddress((void**)&embA, g_embA);
    cudaGetSymbolAddress((void**)&embB, g_embB);
    cudaGetSymbolAddress((void**)&acc,  g_acc);
    cudaGetSymbolAddress((void**)&X,    g_X);
    cudaGetSymbolAddress((void**)&H1,   g_H1);
    cudaGetSymbolAddress((void**)&H2,   g_H2);
    cudaGetSymbolAddress((void**)&sums, g_sums);

    const size_t EMB_BYTES = (size_t)N_NODES * DIM * sizeof(float);
    const int TOT4_BLOCKS = (N_NODES * DIM / 4 + 255) / 256;   // 11250

    // --- multi-hot path (independent of GCN) ---
    rowsums_kernel<<<BATCH, 256>>>(aux, sums);
    cudaMemsetAsync(X, 0, (size_t)BATCH * XCOLS * sizeof(float));
    mh_gemm_kernel<<<dim3(16, 1),  256>>>(aux, 1,    25,   1,  genre_W,    sums, 0, X, 64);
    mh_gemm_kernel<<<dim3(16, 5),  256>>>(aux, 26,   2186, 14, director_W, sums, 1, X, 128);
    mh_gemm_kernel<<<dim3(16, 16), 256>>>(aux, 2212, 8030, 16, actor_W,    sums, 2, X, 192);

    // --- LightGCN: 3 propagation layers ---
    init_emb_kernel<<<TOT4_BLOCKS, 256>>>(user_rel, item_rel, embA, acc);
    int spmm_blocks = (int)(((long)nnz * 16 + 255) / 256);
    float* cur = embA;
    float* nxt = embB;
    for (int layer = 0; layer < 3; layer++) {
        cudaMemsetAsync(nxt, 0, EMB_BYTES);
        spmm_kernel<<<spmm_blocks, 256>>>(cur, nxt, grow, gcol, gval, nnz);
        acc_add_kernel<<<TOT4_BLOCKS, 256>>>(acc, nxt);
        float* tmp = cur; cur = nxt; nxt = tmp;
    }

    // --- assemble X (gathers; 0.25 scale for lightgcn folded in) ---
    gather_kernel<<<BATCH, 64>>>(aux, user_ids, item_ids, rate_tab, gender_tab,
                                 age_tab, occ_tab, area_tab, acc, X);

    // --- MLP ---
    cudaMemsetAsync(H1, 0, (size_t)BATCH * DIM * sizeof(float));
    fc_gemm_kernel<<<dim3(16, 5), 256>>>(X, XCOLS, XCOLS, 4, fc1_W, H1, 64);
    bias_act_kernel<<<(BATCH * DIM + 255) / 256, 256>>>(H1, fc1_b, BATCH * DIM);

    cudaMemsetAsync(H2, 0, (size_t)BATCH * DIM * sizeof(float));
    fc_gemm_kernel<<<dim3(16, 1), 256>>>(H1, 64, 64, 2, fc2_W, H2, 64);
    bias_act_kernel<<<(BATCH * DIM + 255) / 256, 256>>>(H2, fc2_b, BATCH * DIM);

    out_kernel<<<BATCH, 64>>>(H2, out_W, out_b, (float*)d_out);
}

// round 7
// speedup vs baseline: 1.9744x; 1.9744x over previous
#include <cuda_runtime.h>
#include <cstdint>

#define N_USER   150000
#define M_ITEM   30000
#define N_NODES  180000
#define DIM      64
#define BATCH    1024
#define AUX_LD   10246
#define XCOLS    640

// ---------------- scratch (static device memory; no allocs allowed) --------
__device__ float g_embA[(size_t)N_NODES * DIM];   // emb0, later e3 (flagged rows)
__device__ float g_embB[(size_t)N_NODES * DIM];   // e1
__device__ float g_embC[(size_t)N_NODES * DIM];   // e2
__device__ float g_X   [BATCH * XCOLS];
__device__ float g_H1  [BATCH * DIM];
__device__ float g_H2  [BATCH * DIM];
__device__ float g_sums[BATCH * 3];
__device__ unsigned char g_flag[N_NODES];
__device__ int   g_elist[1300000];
__device__ int   g_ecount[1];

// vectorized no-return global float4 reduction (sm_90+)
__device__ __forceinline__ void red_add_v4(float* p, float4 v) {
    asm volatile("red.global.add.v4.f32 [%0], {%1,%2,%3,%4};"
                 :: "l"(p), "f"(v.x), "f"(v.y), "f"(v.z), "f"(v.w) : "memory");
}

// ---------------- LightGCN ------------------------------------------------
// emb0 = concat(user_rel, item_rel)
__global__ void init_emb_kernel(const float* __restrict__ user_rel,
                                const float* __restrict__ item_rel,
                                float* __restrict__ emb) {
    size_t idx = (size_t)blockIdx.x * blockDim.x + threadIdx.x;   // float4 index
    const size_t US4 = (size_t)N_USER * DIM / 4;
    const size_t TOT4 = (size_t)N_NODES * DIM / 4;
    if (idx >= TOT4) return;
    float4 v = (idx < US4) ? reinterpret_cast<const float4*>(user_rel)[idx]
                           : reinterpret_cast<const float4*>(item_rel)[idx - US4];
    reinterpret_cast<float4*>(emb)[idx] = v;
}

// dst[row] += val * src[col]   (16 threads per edge, float4 each)
__global__ void spmm_kernel(const float* __restrict__ src, float* __restrict__ dst,
                            const int* __restrict__ row, const int* __restrict__ col,
                            const float* __restrict__ val, int nnz) {
    long gid = (long)blockIdx.x * blockDim.x + threadIdx.x;
    int e = (int)(gid >> 4);
    int q = (int)(gid & 15);
    if (e >= nnz) return;
    int r = __ldg(row + e);
    int c = __ldg(col + e);
    float v = __ldg(val + e);
    float4 x = *reinterpret_cast<const float4*>(src + (size_t)c * DIM + q * 4);
    float4 y = make_float4(v * x.x, v * x.y, v * x.z, v * x.w);
    red_add_v4(dst + (size_t)r * DIM + q * 4, y);
}

// ---- layer-3 filtering: only batch nodes are ever read ----
__global__ void mark_kernel(const int* __restrict__ uid, const int* __restrict__ iid,
                            unsigned char* __restrict__ flag) {
    int t = blockIdx.x * blockDim.x + threadIdx.x;
    if (t < BATCH) flag[uid[t]] = 1;
    else if (t < 2 * BATCH) flag[N_USER + iid[t - BATCH]] = 1;
}

__global__ void zero_rows_kernel(const int* __restrict__ uid, const int* __restrict__ iid,
                                 float* __restrict__ buf) {
    int b = blockIdx.x;          // 2048
    int d = threadIdx.x;         // 64
    int node = (b < BATCH) ? uid[b] : N_USER + iid[b - BATCH];
    buf[(size_t)node * DIM + d] = 0.f;
}

// warp-ballot compaction of edges whose destination row is flagged
__global__ void edge_filter_kernel(const int* __restrict__ row,
                                   const unsigned char* __restrict__ flag, int nnz,
                                   int* __restrict__ list, int* __restrict__ count) {
    int e = blockIdx.x * blockDim.x + threadIdx.x;
    bool act = false;
    if (e < nnz) act = (flag[__ldg(row + e)] != 0);
    unsigned mask = __ballot_sync(0xffffffffu, act);
    int n = __popc(mask);
    int lane = threadIdx.x & 31;
    int base = 0;
    if (lane == 0 && n) base = atomicAdd(count, n);
    base = __shfl_sync(0xffffffffu, base, 0);
    if (act) {
        int pos = base + __popc(mask & ((1u << lane) - 1));
        list[pos] = e;
    }
}

// SpMM over the compacted edge list (grid-stride; count is dynamic)
__global__ void spmm_list_kernel(const float* __restrict__ src, float* __restrict__ dst,
                                 const int* __restrict__ row, const int* __restrict__ col,
                                 const float* __restrict__ val,
                                 const int* __restrict__ list, const int* __restrict__ count) {
    long total = (long)(*count) * 16;
    long stride = (long)gridDim.x * blockDim.x;
    for (long gid = (long)blockIdx.x * blockDim.x + threadIdx.x; gid < total; gid += stride) {
        int idx = (int)(gid >> 4);
        int q   = (int)(gid & 15);
        int e = __ldg(list + idx);
        int r = __ldg(row + e);
        int c = __ldg(col + e);
        float v = __ldg(val + e);
        float4 x = *reinterpret_cast<const float4*>(src + (size_t)c * DIM + q * 4);
        float4 y = make_float4(v * x.x, v * x.y, v * x.z, v * x.w);
        red_add_v4(dst + (size_t)r * DIM + q * 4, y);
    }
}

// ---------------- multi-hot row sums --------------------------------------
__global__ void rowsums_kernel(const int* __restrict__ aux, float* __restrict__ sums) {
    int b = blockIdx.x;
    int t = threadIdx.x;
    const int* a = aux + (size_t)b * AUX_LD;
    float s0 = 0.f, s1 = 0.f, s2 = 0.f;
    for (int j = 1 + t;    j < 26;    j += 256) s0 += (float)a[j];
    for (int j = 26 + t;   j < 2212;  j += 256) s1 += (float)a[j];
    for (int j = 2212 + t; j < 10242; j += 256) s2 += (float)a[j];
    __shared__ float sd0[256], sd1[256], sd2[256];
    sd0[t] = s0; sd1[t] = s1; sd2[t] = s2;
    __syncthreads();
    for (int off = 128; off > 0; off >>= 1) {
        if (t < off) { sd0[t] += sd0[t + off]; sd1[t] += sd1[t + off]; sd2[t] += sd2[t + off]; }
        __syncthreads();
    }
    if (t == 0) {
        sums[b * 3 + 0] = sd0[0];
        sums[b * 3 + 1] = sd1[0];
        sums[b * 3 + 2] = sd2[0];
    }
}

// ---------------- multi-hot GEMM: X[:,colOut:colOut+64] += (x@W)/rowsum ----
__global__ __launch_bounds__(256)
void mh_gemm_kernel(const int* __restrict__ aux, int colIn, int K, int tilesPerBlock,
                    const float* __restrict__ W,
                    const float* __restrict__ sums, int sumIdx,
                    float* __restrict__ X, int colOut) {
    __shared__ float xs[64][33];
    __shared__ float ws[32][64];
    int t  = threadIdx.x;
    int tx = t & 15;
    int ty = t >> 4;
    int rowBase = blockIdx.x * 64;
    int kStart = blockIdx.y * tilesPerBlock * 32;
    int kEnd   = min(K, kStart + tilesPerBlock * 32);

    float acc[4][4] = {};
    for (int k0 = kStart; k0 < kEnd; k0 += 32) {
        #pragma unroll
        for (int i = 0; i < 8; i++) {
            int l = t + 256 * i;
            int kk = l & 31, rr = l >> 5;
            int kg = k0 + kk;
            xs[rr][kk] = (kg < K) ? (float)aux[(size_t)(rowBase + rr) * AUX_LD + colIn + kg] : 0.f;
        }
        #pragma unroll
        for (int i = 0; i < 8; i++) {
            int l = t + 256 * i;
            int cc = l & 63, kk = l >> 6;
            int kg = k0 + kk;
            ws[kk][cc] = (kg < K) ? W[(size_t)kg * 64 + cc] : 0.f;
        }
        __syncthreads();
        #pragma unroll
        for (int k = 0; k < 32; k++) {
            float4 wv = *reinterpret_cast<float4*>(&ws[k][tx * 4]);
            float a0 = xs[ty * 4 + 0][k];
            float a1 = xs[ty * 4 + 1][k];
            float a2 = xs[ty * 4 + 2][k];
            float a3 = xs[ty * 4 + 3][k];
            acc[0][0] += a0 * wv.x; acc[0][1] += a0 * wv.y; acc[0][2] += a0 * wv.z; acc[0][3] += a0 * wv.w;
            acc[1][0] += a1 * wv.x; acc[1][1] += a1 * wv.y; acc[1][2] += a1 * wv.z; acc[1][3] += a1 * wv.w;
            acc[2][0] += a2 * wv.x; acc[2][1] += a2 * wv.y; acc[2][2] += a2 * wv.z; acc[2][3] += a2 * wv.w;
            acc[3][0] += a3 * wv.x; acc[3][1] += a3 * wv.y; acc[3][2] += a3 * wv.z; acc[3][3] += a3 * wv.w;
        }
        __syncthreads();
    }
    #pragma unroll
    for (int r = 0; r < 4; r++) {
        int row = rowBase + ty * 4 + r;
        float rn = 1.0f / sums[row * 3 + sumIdx];
        float4 v = make_float4(acc[r][0] * rn, acc[r][1] * rn, acc[r][2] * rn, acc[r][3] * rn);
        red_add_v4(&X[(size_t)row * XCOLS + colOut + tx * 4], v);
    }
}

// ---------------- dense GEMM (partial sums into pre-zeroed out) -----------
__global__ __launch_bounds__(256)
void fc_gemm_kernel(const float* __restrict__ A, int lda, int K, int tilesPerBlock,
                    const float* __restrict__ W, float* __restrict__ out, int ldo) {
    __shared__ float xs[64][33];
    __shared__ float ws[32][64];
    int t  = threadIdx.x;
    int tx = t & 15;
    int ty = t >> 4;
    int rowBase = blockIdx.x * 64;
    int kStart = blockIdx.y * tilesPerBlock * 32;
    int kEnd   = min(K, kStart + tilesPerBlock * 32);

    float acc[4][4] = {};
    for (int k0 = kStart; k0 < kEnd; k0 += 32) {
        #pragma unroll
        for (int i = 0; i < 8; i++) {
            int l = t + 256 * i;
            int kk = l & 31, rr = l >> 5;
            int kg = k0 + kk;
            xs[rr][kk] = (kg < K) ? A[(size_t)(rowBase + rr) * lda + kg] : 0.f;
        }
        #pragma unroll
        for (int i = 0; i < 8; i++) {
            int l = t + 256 * i;
            int cc = l & 63, kk = l >> 6;
            int kg = k0 + kk;
            ws[kk][cc] = (kg < K) ? W[(size_t)kg * 64 + cc] : 0.f;
        }
        __syncthreads();
        #pragma unroll
        for (int k = 0; k < 32; k++) {
            float4 wv = *reinterpret_cast<float4*>(&ws[k][tx * 4]);
            float a0 = xs[ty * 4 + 0][k];
            float a1 = xs[ty * 4 + 1][k];
            float a2 = xs[ty * 4 + 2][k];
            float a3 = xs[ty * 4 + 3][k];
            acc[0][0] += a0 * wv.x; acc[0][1] += a0 * wv.y; acc[0][2] += a0 * wv.z; acc[0][3] += a0 * wv.w;
            acc[1][0] += a1 * wv.x; acc[1][1] += a1 * wv.y; acc[1][2] += a1 * wv.z; acc[1][3] += a1 * wv.w;
            acc[2][0] += a2 * wv.x; acc[2][1] += a2 * wv.y; acc[2][2] += a2 * wv.z; acc[2][3] += a2 * wv.w;
            acc[3][0] += a3 * wv.x; acc[3][1] += a3 * wv.y; acc[3][2] += a3 * wv.z; acc[3][3] += a3 * wv.w;
        }
        __syncthreads();
    }
    #pragma unroll
    for (int r = 0; r < 4; r++) {
        int row = rowBase + ty * 4 + r;
        float4 v = make_float4(acc[r][0], acc[r][1], acc[r][2], acc[r][3]);
        red_add_v4(&out[(size_t)row * ldo + tx * 4], v);
    }
}

__global__ void bias_act_kernel(float* __restrict__ h, const float* __restrict__ b, int n) {
    int i = blockIdx.x * blockDim.x + threadIdx.x;
    if (i >= n) return;
    float v = h[i] + b[i & 63];
    h[i] = v > 0.f ? v : 0.f;
}

// ---------------- gathers: tables + LightGCN sum (emb0+e1+e2+e3)/4 --------
__global__ void gather_kernel(const int* __restrict__ aux,
                              const int* __restrict__ uid, const int* __restrict__ iid,
                              const float* __restrict__ rate_tab,
                              const float* __restrict__ gender_tab,
                              const float* __restrict__ age_tab,
                              const float* __restrict__ occ_tab,
                              const float* __restrict__ area_tab,
                              const float* __restrict__ user_rel,
                              const float* __restrict__ item_rel,
                              const float* __restrict__ e1,
                              const float* __restrict__ e2,
                              const float* __restrict__ e3,
                              float* __restrict__ X) {
    int b = blockIdx.x;
    int d = threadIdx.x;   // 64
    const int* a = aux + (size_t)b * AUX_LD;
    float* xr = X + (size_t)b * XCOLS;
    xr[0   + d] = rate_tab  [(size_t)a[0]     * 64 + d];
    xr[256 + d] = gender_tab[(size_t)a[10242] * 64 + d];
    xr[320 + d] = age_tab   [(size_t)a[10243] * 64 + d];
    xr[384 + d] = occ_tab   [(size_t)a[10244] * 64 + d];
    xr[448 + d] = area_tab  [(size_t)a[10245] * 64 + d];
    int u  = uid[b];
    int it = iid[b];
    size_t un = (size_t)u * 64 + d;
    size_t in_ = ((size_t)N_USER + it) * 64 + d;
    xr[512 + d] = 0.25f * (user_rel[un] + e1[un] + e2[un] + e3[un]);
    xr[576 + d] = 0.25f * (item_rel[(size_t)it * 64 + d] + e1[in_] + e2[in_] + e3[in_]);
}

// ---------------- final dot -----------------------------------------------
__global__ void out_kernel(const float* __restrict__ H2, const float* __restrict__ w,
                           const float* __restrict__ ob, float* __restrict__ out) {
    int b = blockIdx.x;
    int t = threadIdx.x;   // 64
    __shared__ float s[64];
    s[t] = H2[(size_t)b * 64 + t] * w[t];
    __syncthreads();
    for (int off = 32; off > 0; off >>= 1) {
        if (t < off) s[t] += s[t + off];
        __syncthreads();
    }
    if (t == 0) out[b] = s[0] + ob[0];
}

// ---------------- launch ---------------------------------------------------
extern "C" void kernel_launch(void* const* d_in, const int* in_sizes, int n_in,
                              void* d_out, int out_size) {
    const int*   aux       = (const int*)  d_in[0];
    const int*   user_ids  = (const int*)  d_in[1];
    const int*   item_ids  = (const int*)  d_in[2];
    const int*   grow      = (const int*)  d_in[3];
    const int*   gcol      = (const int*)  d_in[4];
    const float* gval      = (const float*)d_in[5];
    const float* rate_tab  = (const float*)d_in[6];
    const float* genre_W   = (const float*)d_in[7];
    const float* director_W= (const float*)d_in[8];
    const float* actor_W   = (const float*)d_in[9];
    const float* gender_tab= (const float*)d_in[10];
    const float* age_tab   = (const float*)d_in[11];
    const float* occ_tab   = (const float*)d_in[12];
    const float* area_tab  = (const float*)d_in[13];
    const float* user_rel  = (const float*)d_in[14];
    const float* item_rel  = (const float*)d_in[15];
    const float* fc1_W     = (const float*)d_in[16];
    const float* fc1_b     = (const float*)d_in[17];
    const float* fc2_W     = (const float*)d_in[18];
    const float* fc2_b     = (const float*)d_in[19];
    const float* out_W     = (const float*)d_in[20];
    const float* out_b     = (const float*)d_in[21];
    int nnz = in_sizes[3];

    float *embA, *embB, *embC, *X, *H1, *H2, *sums;
    unsigned char* flag;
    int *elist, *ecount;
    cudaGetSymbolAddress((void**)&embA,  g_embA);
    cudaGetSymbolAddress((void**)&embB,  g_embB);
    cudaGetSymbolAddress((void**)&embC,  g_embC);
    cudaGetSymbolAddress((void**)&X,     g_X);
    cudaGetSymbolAddress((void**)&H1,    g_H1);
    cudaGetSymbolAddress((void**)&H2,    g_H2);
    cudaGetSymbolAddress((void**)&sums,  g_sums);
    cudaGetSymbolAddress((void**)&flag,  g_flag);
    cudaGetSymbolAddress((void**)&elist, g_elist);
    cudaGetSymbolAddress((void**)&ecount,g_ecount);

    const size_t EMB_BYTES = (size_t)N_NODES * DIM * sizeof(float);
    const int TOT4_BLOCKS = (N_NODES * DIM / 4 + 255) / 256;

    // --- multi-hot path (deep K-split for full-chip occupancy) ---
    rowsums_kernel<<<BATCH, 256>>>(aux, sums);
    cudaMemsetAsync(X, 0, (size_t)BATCH * XCOLS * sizeof(float));
    mh_gemm_kernel<<<dim3(16, 1),  256>>>(aux, 1,    25,   1, genre_W,    sums, 0, X, 64);
    mh_gemm_kernel<<<dim3(16, 14), 256>>>(aux, 26,   2186, 5, director_W, sums, 1, X, 128);
    mh_gemm_kernel<<<dim3(16, 28), 256>>>(aux, 2212, 8030, 9, actor_W,    sums, 2, X, 192);

    // --- LightGCN ---
    init_emb_kernel<<<TOT4_BLOCKS, 256>>>(user_rel, item_rel, embA);

    // flags + filtered edge list for layer 3 (only batch nodes are read)
    cudaMemsetAsync(flag, 0, N_NODES);
    cudaMemsetAsync(ecount, 0, sizeof(int));
    mark_kernel<<<(2 * BATCH + 255) / 256, 256>>>(user_ids, item_ids, flag);
    edge_filter_kernel<<<(nnz + 255) / 256, 256>>>(grow, flag, nnz, elist, ecount);

    int spmm_blocks = (int)(((long)nnz * 16 + 255) / 256);
    // layer 1: e1 = P @ emb0
    cudaMemsetAsync(embB, 0, EMB_BYTES);
    spmm_kernel<<<spmm_blocks, 256>>>(embA, embB, grow, gcol, gval, nnz);
    // layer 2: e2 = P @ e1
    cudaMemsetAsync(embC, 0, EMB_BYTES);
    spmm_kernel<<<spmm_blocks, 256>>>(embB, embC, grow, gcol, gval, nnz);
    // layer 3 (filtered): e3 = P @ e2, only at flagged rows (into embA)
    zero_rows_kernel<<<2 * BATCH, 64>>>(user_ids, item_ids, embA);
    spmm_list_kernel<<<2048, 256>>>(embC, embA, grow, gcol, gval, elist, ecount);

    // --- assemble X ---
    gather_kernel<<<BATCH, 64>>>(aux, user_ids, item_ids, rate_tab, gender_tab,
                                 age_tab, occ_tab, area_tab,
                                 user_rel, item_rel, embB, embC, embA, X);

    // --- MLP ---
    cudaMemsetAsync(H1, 0, (size_t)BATCH * DIM * sizeof(float));
    fc_gemm_kernel<<<dim3(16, 20), 256>>>(X, XCOLS, XCOLS, 1, fc1_W, H1, 64);
    bias_act_kernel<<<(BATCH * DIM + 255) / 256, 256>>>(H1, fc1_b, BATCH * DIM);

    cudaMemsetAsync(H2, 0, (size_t)BATCH * DIM * sizeof(float));
    fc_gemm_kernel<<<dim3(16, 2), 256>>>(H1, 64, 64, 1, fc2_W, H2, 64);
    bias_act_kernel<<<(BATCH * DIM + 255) / 256, 256>>>(H2, fc2_b, BATCH * DIM);

    out_kernel<<<BATCH, 64>>>(H2, out_W, out_b, (float*)d_out);
}

// round 8
// speedup vs baseline: 2.1944x; 1.1114x over previous
#include <cuda_runtime.h>
#include <cstdint>

#define N_USER   150000
#define M_ITEM   30000
#define N_NODES  180000
#define DIM      64
#define BATCH    1024
#define AUX_LD   10246
#define XCOLS    640

// ---------------- scratch (static device memory; no allocs allowed) --------
__device__ float g_embA[(size_t)N_NODES * DIM];   // emb0, later e3 (flagged rows)
__device__ float g_embB[(size_t)N_NODES * DIM];   // e1
__device__ float g_embC[(size_t)N_NODES * DIM];   // e2 (valid at flag2 rows only)
__device__ float g_X   [BATCH * XCOLS];
__device__ float g_H1  [BATCH * DIM];
__device__ float g_H2  [BATCH * DIM];
__device__ float g_sums[BATCH * 3];
__device__ unsigned char g_flag [N_NODES];
__device__ unsigned char g_flag2[N_NODES];
__device__ int   g_elist [1300000];   // layer-3 edges (row flagged)
__device__ int   g_elist2[1300000];   // layer-2 edges (row flag2)
__device__ int   g_nlist2[N_NODES];   // nodes with flag2 (for zeroing embC)
__device__ int   g_cnt[4];            // [0]=elist, [1]=elist2, [2]=nlist2

// vectorized no-return global float4 reduction (sm_90+)
__device__ __forceinline__ void red_add_v4(float* p, float4 v) {
    asm volatile("red.global.add.v4.f32 [%0], {%1,%2,%3,%4};"
                 :: "l"(p), "f"(v.x), "f"(v.y), "f"(v.z), "f"(v.w) : "memory");
}

// ---------------- LightGCN ------------------------------------------------
__global__ void init_emb_kernel(const float* __restrict__ user_rel,
                                const float* __restrict__ item_rel,
                                float* __restrict__ emb) {
    size_t idx = (size_t)blockIdx.x * blockDim.x + threadIdx.x;   // float4 index
    const size_t US4 = (size_t)N_USER * DIM / 4;
    const size_t TOT4 = (size_t)N_NODES * DIM / 4;
    if (idx >= TOT4) return;
    float4 v = (idx < US4) ? reinterpret_cast<const float4*>(user_rel)[idx]
                           : reinterpret_cast<const float4*>(item_rel)[idx - US4];
    reinterpret_cast<float4*>(emb)[idx] = v;
}

// dst[row] += val * src[col]   (16 threads per edge, float4 each)
__global__ void spmm_kernel(const float* __restrict__ src, float* __restrict__ dst,
                            const int* __restrict__ row, const int* __restrict__ col,
                            const float* __restrict__ val, int nnz) {
    long gid = (long)blockIdx.x * blockDim.x + threadIdx.x;
    int e = (int)(gid >> 4);
    int q = (int)(gid & 15);
    if (e >= nnz) return;
    int r = __ldg(row + e);
    int c = __ldg(col + e);
    float v = __ldg(val + e);
    float4 x = *reinterpret_cast<const float4*>(src + (size_t)c * DIM + q * 4);
    float4 y = make_float4(v * x.x, v * x.y, v * x.z, v * x.w);
    red_add_v4(dst + (size_t)r * DIM + q * 4, y);
}

// ---- filtering machinery ----
// batch nodes get flag + flag2
__global__ void mark_kernel(const int* __restrict__ uid, const int* __restrict__ iid,
                            unsigned char* __restrict__ flag, unsigned char* __restrict__ flag2) {
    int t = blockIdx.x * blockDim.x + threadIdx.x;
    if (t < BATCH) { int n = uid[t]; flag[n] = 1; flag2[n] = 1; }
    else if (t < 2 * BATCH) { int n = N_USER + iid[t - BATCH]; flag[n] = 1; flag2[n] = 1; }
}

// fused: compact layer-3 edges (row flagged) AND mark flag2[col] for those edges
__global__ void filter_mark2_kernel(const int* __restrict__ row, const int* __restrict__ col,
                                    const unsigned char* __restrict__ flag, int nnz,
                                    int* __restrict__ list, int* __restrict__ count,
                                    unsigned char* __restrict__ flag2) {
    int e = blockIdx.x * blockDim.x + threadIdx.x;
    bool act = false;
    if (e < nnz) act = (flag[__ldg(row + e)] != 0);
    if (act) flag2[__ldg(col + e)] = 1;
    unsigned mask = __ballot_sync(0xffffffffu, act);
    int n = __popc(mask);
    int lane = threadIdx.x & 31;
    int base = 0;
    if (lane == 0 && n) base = atomicAdd(count, n);
    base = __shfl_sync(0xffffffffu, base, 0);
    if (act) list[base + __popc(mask & ((1u << lane) - 1))] = e;
}

// compact layer-2 edges (row in flag2)
__global__ void filter2_kernel(const int* __restrict__ row,
                               const unsigned char* __restrict__ flag2, int nnz,
                               int* __restrict__ list, int* __restrict__ count) {
    int e = blockIdx.x * blockDim.x + threadIdx.x;
    bool act = false;
    if (e < nnz) act = (flag2[__ldg(row + e)] != 0);
    unsigned mask = __ballot_sync(0xffffffffu, act);
    int n = __popc(mask);
    int lane = threadIdx.x & 31;
    int base = 0;
    if (lane == 0 && n) base = atomicAdd(count, n);
    base = __shfl_sync(0xffffffffu, base, 0);
    if (act) list[base + __popc(mask & ((1u << lane) - 1))] = e;
}

// compact flag2 nodes into a list (for targeted zeroing of embC)
__global__ void node_compact_kernel(const unsigned char* __restrict__ flag2,
                                    int* __restrict__ list, int* __restrict__ count) {
    int n = blockIdx.x * blockDim.x + threadIdx.x;
    bool act = (n < N_NODES) && (flag2[n] != 0);
    unsigned mask = __ballot_sync(0xffffffffu, act);
    int c = __popc(mask);
    int lane = threadIdx.x & 31;
    int base = 0;
    if (lane == 0 && c) base = atomicAdd(count, c);
    base = __shfl_sync(0xffffffffu, base, 0);
    if (act) list[base + __popc(mask & ((1u << lane) - 1))] = n;
}

// zero rows named in list (16 float4 per node)
__global__ void zero_list_kernel(float* __restrict__ buf,
                                 const int* __restrict__ list, const int* __restrict__ count) {
    long total = (long)(*count) * 16;
    long stride = (long)gridDim.x * blockDim.x;
    for (long gid = (long)blockIdx.x * blockDim.x + threadIdx.x; gid < total; gid += stride) {
        int node = __ldg(list + (int)(gid >> 4));
        int q = (int)(gid & 15);
        reinterpret_cast<float4*>(buf + (size_t)node * DIM)[q] = make_float4(0.f, 0.f, 0.f, 0.f);
    }
}

__global__ void zero_rows_kernel(const int* __restrict__ uid, const int* __restrict__ iid,
                                 float* __restrict__ buf) {
    int b = blockIdx.x;          // 2048
    int d = threadIdx.x;         // 64
    int node = (b < BATCH) ? uid[b] : N_USER + iid[b - BATCH];
    buf[(size_t)node * DIM + d] = 0.f;
}

// SpMM over a compacted edge list (grid-stride; count is dynamic)
__global__ void spmm_list_kernel(const float* __restrict__ src, float* __restrict__ dst,
                                 const int* __restrict__ row, const int* __restrict__ col,
                                 const float* __restrict__ val,
                                 const int* __restrict__ list, const int* __restrict__ count) {
    long total = (long)(*count) * 16;
    long stride = (long)gridDim.x * blockDim.x;
    for (long gid = (long)blockIdx.x * blockDim.x + threadIdx.x; gid < total; gid += stride) {
        int idx = (int)(gid >> 4);
        int q   = (int)(gid & 15);
        int e = __ldg(list + idx);
        int r = __ldg(row + e);
        int c = __ldg(col + e);
        float v = __ldg(val + e);
        float4 x = *reinterpret_cast<const float4*>(src + (size_t)c * DIM + q * 4);
        float4 y = make_float4(v * x.x, v * x.y, v * x.z, v * x.w);
        red_add_v4(dst + (size_t)r * DIM + q * 4, y);
    }
}

// ---------------- multi-hot row sums --------------------------------------
__global__ void rowsums_kernel(const int* __restrict__ aux, float* __restrict__ sums) {
    int b = blockIdx.x;
    int t = threadIdx.x;
    const int* a = aux + (size_t)b * AUX_LD;
    float s0 = 0.f, s1 = 0.f, s2 = 0.f;
    for (int j = 1 + t;    j < 26;    j += 256) s0 += (float)a[j];
    for (int j = 26 + t;   j < 2212;  j += 256) s1 += (float)a[j];
    for (int j = 2212 + t; j < 10242; j += 256) s2 += (float)a[j];
    __shared__ float sd0[256], sd1[256], sd2[256];
    sd0[t] = s0; sd1[t] = s1; sd2[t] = s2;
    __syncthreads();
    for (int off = 128; off > 0; off >>= 1) {
        if (t < off) { sd0[t] += sd0[t + off]; sd1[t] += sd1[t + off]; sd2[t] += sd2[t + off]; }
        __syncthreads();
    }
    if (t == 0) {
        sums[b * 3 + 0] = sd0[0];
        sums[b * 3 + 1] = sd1[0];
        sums[b * 3 + 2] = sd2[0];
    }
}

// ---------------- multi-hot GEMM: X[:,colOut:colOut+64] += (x@W)/rowsum ----
// A tile transposed in smem: xs[k][row], stride 68 (16B aligned); inner loop
// does ONE LDS.128 for A quad + ONE LDS.128 for W quad per k-step.
__global__ __launch_bounds__(256)
void mh_gemm_kernel(const int* __restrict__ aux, int colIn, int K, int tilesPerBlock,
                    const float* __restrict__ W,
                    const float* __restrict__ sums, int sumIdx,
                    float* __restrict__ X, int colOut) {
    __shared__ float xs[32][68];
    __shared__ float ws[32][64];
    int t  = threadIdx.x;
    int tx = t & 15;
    int ty = t >> 4;
    int rowBase = blockIdx.x * 64;
    int kStart = blockIdx.y * tilesPerBlock * 32;
    int kEnd   = min(K, kStart + tilesPerBlock * 32);

    float acc[4][4] = {};
    for (int k0 = kStart; k0 < kEnd; k0 += 32) {
        #pragma unroll
        for (int i = 0; i < 8; i++) {
            int l = t + 256 * i;
            int kk = l & 31, rr = l >> 5;
            int kg = k0 + kk;
            xs[kk][rr] = (kg < K) ? (float)aux[(size_t)(rowBase + rr) * AUX_LD + colIn + kg] : 0.f;
        }
        #pragma unroll
        for (int i = 0; i < 8; i++) {
            int l = t + 256 * i;
            int cc = l & 63, kk = l >> 6;
            int kg = k0 + kk;
            ws[kk][cc] = (kg < K) ? W[(size_t)kg * 64 + cc] : 0.f;
        }
        __syncthreads();
        #pragma unroll
        for (int k = 0; k < 32; k++) {
            float4 wv = *reinterpret_cast<float4*>(&ws[k][tx * 4]);
            float4 av = *reinterpret_cast<float4*>(&xs[k][ty * 4]);
            acc[0][0] += av.x * wv.x; acc[0][1] += av.x * wv.y; acc[0][2] += av.x * wv.z; acc[0][3] += av.x * wv.w;
            acc[1][0] += av.y * wv.x; acc[1][1] += av.y * wv.y; acc[1][2] += av.y * wv.z; acc[1][3] += av.y * wv.w;
            acc[2][0] += av.z * wv.x; acc[2][1] += av.z * wv.y; acc[2][2] += av.z * wv.z; acc[2][3] += av.z * wv.w;
            acc[3][0] += av.w * wv.x; acc[3][1] += av.w * wv.y; acc[3][2] += av.w * wv.z; acc[3][3] += av.w * wv.w;
        }
        __syncthreads();
    }
    #pragma unroll
    for (int r = 0; r < 4; r++) {
        int row = rowBase + ty * 4 + r;
        float rn = 1.0f / sums[row * 3 + sumIdx];
        float4 v = make_float4(acc[r][0] * rn, acc[r][1] * rn, acc[r][2] * rn, acc[r][3] * rn);
        red_add_v4(&X[(size_t)row * XCOLS + colOut + tx * 4], v);
    }
}

// ---------------- dense GEMM (partial sums into pre-zeroed out) -----------
__global__ __launch_bounds__(256)
void fc_gemm_kernel(const float* __restrict__ A, int lda, int K, int tilesPerBlock,
                    const float* __restrict__ W, float* __restrict__ out, int ldo) {
    __shared__ float xs[32][68];
    __shared__ float ws[32][64];
    int t  = threadIdx.x;
    int tx = t & 15;
    int ty = t >> 4;
    int rowBase = blockIdx.x * 64;
    int kStart = blockIdx.y * tilesPerBlock * 32;
    int kEnd   = min(K, kStart + tilesPerBlock * 32);

    float acc[4][4] = {};
    for (int k0 = kStart; k0 < kEnd; k0 += 32) {
        #pragma unroll
        for (int i = 0; i < 8; i++) {
            int l = t + 256 * i;
            int kk = l & 31, rr = l >> 5;
            int kg = k0 + kk;
            xs[kk][rr] = (kg < K) ? A[(size_t)(rowBase + rr) * lda + kg] : 0.f;
        }
        #pragma unroll
        for (int i = 0; i < 8; i++) {
            int l = t + 256 * i;
            int cc = l & 63, kk = l >> 6;
            int kg = k0 + kk;
            ws[kk][cc] = (kg < K) ? W[(size_t)kg * 64 + cc] : 0.f;
        }
        __syncthreads();
        #pragma unroll
        for (int k = 0; k < 32; k++) {
            float4 wv = *reinterpret_cast<float4*>(&ws[k][tx * 4]);
            float4 av = *reinterpret_cast<float4*>(&xs[k][ty * 4]);
            acc[0][0] += av.x * wv.x; acc[0][1] += av.x * wv.y; acc[0][2] += av.x * wv.z; acc[0][3] += av.x * wv.w;
            acc[1][0] += av.y * wv.x; acc[1][1] += av.y * wv.y; acc[1][2] += av.y * wv.z; acc[1][3] += av.y * wv.w;
            acc[2][0] += av.z * wv.x; acc[2][1] += av.z * wv.y; acc[2][2] += av.z * wv.z; acc[2][3] += av.z * wv.w;
            acc[3][0] += av.w * wv.x; acc[3][1] += av.w * wv.y; acc[3][2] += av.w * wv.z; acc[3][3] += av.w * wv.w;
        }
        __syncthreads();
    }
    #pragma unroll
    for (int r = 0; r < 4; r++) {
        int row = rowBase + ty * 4 + r;
        float4 v = make_float4(acc[r][0], acc[r][1], acc[r][2], acc[r][3]);
        red_add_v4(&out[(size_t)row * ldo + tx * 4], v);
    }
}

__global__ void bias_act_kernel(float* __restrict__ h, const float* __restrict__ b, int n) {
    int i = blockIdx.x * blockDim.x + threadIdx.x;
    if (i >= n) return;
    float v = h[i] + b[i & 63];
    h[i] = v > 0.f ? v : 0.f;
}

// ---------------- gathers: tables + LightGCN sum (emb0+e1+e2+e3)/4 --------
__global__ void gather_kernel(const int* __restrict__ aux,
                              const int* __restrict__ uid, const int* __restrict__ iid,
                              const float* __restrict__ rate_tab,
                              const float* __restrict__ gender_tab,
                              const float* __restrict__ age_tab,
                              const float* __restrict__ occ_tab,
                              const float* __restrict__ area_tab,
                              const float* __restrict__ user_rel,
                              const float* __restrict__ item_rel,
                              const float* __restrict__ e1,
                              const float* __restrict__ e2,
                              const float* __restrict__ e3,
                              float* __restrict__ X) {
    int b = blockIdx.x;
    int d = threadIdx.x;   // 64
    const int* a = aux + (size_t)b * AUX_LD;
    float* xr = X + (size_t)b * XCOLS;
    xr[0   + d] = rate_tab  [(size_t)a[0]     * 64 + d];
    xr[256 + d] = gender_tab[(size_t)a[10242] * 64 + d];
    xr[320 + d] = age_tab   [(size_t)a[10243] * 64 + d];
    xr[384 + d] = occ_tab   [(size_t)a[10244] * 64 + d];
    xr[448 + d] = area_tab  [(size_t)a[10245] * 64 + d];
    int u  = uid[b];
    int it = iid[b];
    size_t un = (size_t)u * 64 + d;
    size_t in_ = ((size_t)N_USER + it) * 64 + d;
    xr[512 + d] = 0.25f * (user_rel[un] + e1[un] + e2[un] + e3[un]);
    xr[576 + d] = 0.25f * (item_rel[(size_t)it * 64 + d] + e1[in_] + e2[in_] + e3[in_]);
}

// ---------------- final dot -----------------------------------------------
__global__ void out_kernel(const float* __restrict__ H2, const float* __restrict__ w,
                           const float* __restrict__ ob, float* __restrict__ out) {
    int b = blockIdx.x;
    int t = threadIdx.x;   // 64
    __shared__ float s[64];
    s[t] = H2[(size_t)b * 64 + t] * w[t];
    __syncthreads();
    for (int off = 32; off > 0; off >>= 1) {
        if (t < off) s[t] += s[t + off];
        __syncthreads();
    }
    if (t == 0) out[b] = s[0] + ob[0];
}

// ---------------- launch ---------------------------------------------------
extern "C" void kernel_launch(void* const* d_in, const int* in_sizes, int n_in,
                              void* d_out, int out_size) {
    const int*   aux       = (const int*)  d_in[0];
    const int*   user_ids  = (const int*)  d_in[1];
    const int*   item_ids  = (const int*)  d_in[2];
    const int*   grow      = (const int*)  d_in[3];
    const int*   gcol      = (const int*)  d_in[4];
    const float* gval      = (const float*)d_in[5];
    const float* rate_tab  = (const float*)d_in[6];
    const float* genre_W   = (const float*)d_in[7];
    const float* director_W= (const float*)d_in[8];
    const float* actor_W   = (const float*)d_in[9];
    const float* gender_tab= (const float*)d_in[10];
    const float* age_tab   = (const float*)d_in[11];
    const float* occ_tab   = (const float*)d_in[12];
    const float* area_tab  = (const float*)d_in[13];
    const float* user_rel  = (const float*)d_in[14];
    const float* item_rel  = (const float*)d_in[15];
    const float* fc1_W     = (const float*)d_in[16];
    const float* fc1_b     = (const float*)d_in[17];
    const float* fc2_W     = (const float*)d_in[18];
    const float* fc2_b     = (const float*)d_in[19];
    const float* out_W     = (const float*)d_in[20];
    const float* out_b     = (const float*)d_in[21];
    int nnz = in_sizes[3];

    float *embA, *embB, *embC, *X, *H1, *H2, *sums;
    unsigned char *flag, *flag2;
    int *elist, *elist2, *nlist2, *cnt;
    cudaGetSymbolAddress((void**)&embA,  g_embA);
    cudaGetSymbolAddress((void**)&embB,  g_embB);
    cudaGetSymbolAddress((void**)&embC,  g_embC);
    cudaGetSymbolAddress((void**)&X,     g_X);
    cudaGetSymbolAddress((void**)&H1,    g_H1);
    cudaGetSymbolAddress((void**)&H2,    g_H2);
    cudaGetSymbolAddress((void**)&sums,  g_sums);
    cudaGetSymbolAddress((void**)&flag,  g_flag);
    cudaGetSymbolAddress((void**)&flag2, g_flag2);
    cudaGetSymbolAddress((void**)&elist, g_elist);
    cudaGetSymbolAddress((void**)&elist2,g_elist2);
    cudaGetSymbolAddress((void**)&nlist2,g_nlist2);
    cudaGetSymbolAddress((void**)&cnt,   g_cnt);

    const size_t EMB_BYTES = (size_t)N_NODES * DIM * sizeof(float);
    const int TOT4_BLOCKS = (N_NODES * DIM / 4 + 255) / 256;
    const int EB = (nnz + 255) / 256;

    // --- multi-hot path (independent of GCN) ---
    rowsums_kernel<<<BATCH, 256>>>(aux, sums);
    cudaMemsetAsync(X, 0, (size_t)BATCH * XCOLS * sizeof(float));
    mh_gemm_kernel<<<dim3(16, 1),  256>>>(aux, 1,    25,   1, genre_W,    sums, 0, X, 64);
    mh_gemm_kernel<<<dim3(16, 14), 256>>>(aux, 26,   2186, 5, director_W, sums, 1, X, 128);
    mh_gemm_kernel<<<dim3(16, 28), 256>>>(aux, 2212, 8030, 9, actor_W,    sums, 2, X, 192);

    // --- flags + filtered edge/node lists (independent of emb compute) ---
    cudaMemsetAsync(flag,  0, N_NODES);
    cudaMemsetAsync(flag2, 0, N_NODES);
    cudaMemsetAsync(cnt, 0, 3 * sizeof(int));
    mark_kernel<<<(2 * BATCH + 255) / 256, 256>>>(user_ids, item_ids, flag, flag2);
    filter_mark2_kernel<<<EB, 256>>>(grow, gcol, flag, nnz, elist, cnt + 0, flag2);
    filter2_kernel<<<EB, 256>>>(grow, flag2, nnz, elist2, cnt + 1);
    node_compact_kernel<<<(N_NODES + 255) / 256, 256>>>(flag2, nlist2, cnt + 2);

    // --- LightGCN ---
    init_emb_kernel<<<TOT4_BLOCKS, 256>>>(user_rel, item_rel, embA);

    // layer 1 (full): e1 = P @ emb0
    cudaMemsetAsync(embB, 0, EMB_BYTES);
    int spmm_blocks = (int)(((long)nnz * 16 + 255) / 256);
    spmm_kernel<<<spmm_blocks, 256>>>(embA, embB, grow, gcol, gval, nnz);

    // layer 2 (filtered to flag2 rows): e2 = P @ e1
    zero_list_kernel<<<1024, 256>>>(embC, nlist2, cnt + 2);
    spmm_list_kernel<<<2048, 256>>>(embB, embC, grow, gcol, gval, elist2, cnt + 1);

    // layer 3 (filtered to batch rows): e3 = P @ e2  (into embA)
    zero_rows_kernel<<<2 * BATCH, 64>>>(user_ids, item_ids, embA);
    spmm_list_kernel<<<2048, 256>>>(embC, embA, grow, gcol, gval, elist, cnt + 0);

    // --- assemble X ---
    gather_kernel<<<BATCH, 64>>>(aux, user_ids, item_ids, rate_tab, gender_tab,
                                 age_tab, occ_tab, area_tab,
                                 user_rel, item_rel, embB, embC, embA, X);

    // --- MLP ---
    cudaMemsetAsync(H1, 0, (size_t)BATCH * DIM * sizeof(float));
    fc_gemm_kernel<<<dim3(16, 20), 256>>>(X, XCOLS, XCOLS, 1, fc1_W, H1, 64);
    bias_act_kernel<<<(BATCH * DIM + 255) / 256, 256>>>(H1, fc1_b, BATCH * DIM);

    cudaMemsetAsync(H2, 0, (size_t)BATCH * DIM * sizeof(float));
    fc_gemm_kernel<<<dim3(16, 2), 256>>>(H1, 64, 64, 1, fc2_W, H2, 64);
    bias_act_kernel<<<(BATCH * DIM + 255) / 256, 256>>>(H2, fc2_b, BATCH * DIM);

    out_kernel<<<BATCH, 64>>>(H2, out_W, out_b, (float*)d_out);
}

// round 9
// speedup vs baseline: 2.7601x; 1.2578x over previous
#include <cuda_runtime.h>
#include <cstdint>

#define N_USER   150000
#define M_ITEM   30000
#define N_NODES  180000
#define DIM      64
#define BATCH    1024
#define AUX_LD   10246
#define XCOLS    640
#define MAXE     1300000

// ---------------- scratch (static device memory; no allocs allowed) --------
__device__ float g_embB[(size_t)N_NODES * DIM];   // e1 (full)
__device__ float g_embC[(size_t)N_NODES * DIM];   // e2 (valid at flag2 rows)
__device__ float g_e3  [2 * BATCH * DIM];         // e3 at batch positions
__device__ float g_X   [BATCH * XCOLS];
__device__ float g_H1  [BATCH * DIM];
__device__ float g_H2  [BATCH * DIM];
__device__ float g_sums[BATCH * 3];
__device__ unsigned char g_flag2[N_NODES];
__device__ int   g_nlist2[N_NODES];
__device__ int   g_cnt[4];
// CSR
__device__ int   g_deg   [N_NODES];
__device__ int   g_rowptr[N_NODES + 1];
__device__ int   g_cursor[N_NODES];
__device__ int   g_csr_col[MAXE];
__device__ float g_csr_val[MAXE];
__device__ int   g_bsum [256];
__device__ int   g_boffs[256];

// vectorized no-return global float4 reduction (sm_90+)
__device__ __forceinline__ void red_add_v4(float* p, float4 v) {
    asm volatile("red.global.add.v4.f32 [%0], {%1,%2,%3,%4};"
                 :: "l"(p), "f"(v.x), "f"(v.y), "f"(v.z), "f"(v.w) : "memory");
}

// ================= CSR build =================
__global__ void hist_kernel(const int* __restrict__ row, int nnz, int* __restrict__ deg) {
    int e = blockIdx.x * blockDim.x + threadIdx.x;
    if (e < nnz) atomicAdd(&deg[__ldg(row + e)], 1);
}

// per-1024-chunk totals
__global__ void bsum_kernel(const int* __restrict__ deg, int* __restrict__ bsum) {
    int b = blockIdx.x, t = threadIdx.x;
    int i0 = b * 1024 + t * 4;
    int s = 0;
    #pragma unroll
    for (int k = 0; k < 4; k++) {
        int i = i0 + k;
        if (i < N_NODES) s += deg[i];
    }
    __shared__ int sd[256];
    sd[t] = s;
    __syncthreads();
    for (int off = 128; off > 0; off >>= 1) {
        if (t < off) sd[t] += sd[t + off];
        __syncthreads();
    }
    if (t == 0) bsum[b] = sd[0];
}

// exclusive scan of up to 256 block sums (1 block)
__global__ void bscan_kernel(const int* __restrict__ bsum, int* __restrict__ boffs,
                             int nb, int nnz, int* __restrict__ rowptr) {
    int t = threadIdx.x;
    __shared__ int s[256];
    int orig = (t < nb) ? bsum[t] : 0;
    s[t] = orig;
    __syncthreads();
    for (int off = 1; off < 256; off <<= 1) {
        int v = (t >= off) ? s[t - off] : 0;
        __syncthreads();
        s[t] += v;
        __syncthreads();
    }
    boffs[t] = s[t] - orig;
    if (t == 0) rowptr[N_NODES] = nnz;
}

// full exclusive scan: rowptr[i] = prefix(deg), cursor[i] = same
__global__ void scan_kernel(const int* __restrict__ deg, const int* __restrict__ boffs,
                            int* __restrict__ rowptr, int* __restrict__ cursor) {
    int t = threadIdx.x;
    int lane = t & 31, wid = t >> 5;
    int i0 = blockIdx.x * 1024 + t * 4;
    int d0 = (i0 + 0 < N_NODES) ? deg[i0 + 0] : 0;
    int d1 = (i0 + 1 < N_NODES) ? deg[i0 + 1] : 0;
    int d2 = (i0 + 2 < N_NODES) ? deg[i0 + 2] : 0;
    int d3 = (i0 + 3 < N_NODES) ? deg[i0 + 3] : 0;
    int ts = d0 + d1 + d2 + d3;
    int x = ts;
    #pragma unroll
    for (int off = 1; off < 32; off <<= 1) {
        int y = __shfl_up_sync(0xffffffffu, x, off);
        if (lane >= off) x += y;
    }
    int lane_excl = x - ts;
    __shared__ int wtot[8], woff[8];
    if (lane == 31) wtot[wid] = x;
    __syncthreads();
    if (t == 0) {
        int r = 0;
        #pragma unroll
        for (int k = 0; k < 8; k++) { woff[k] = r; r += wtot[k]; }
    }
    __syncthreads();
    int p = boffs[blockIdx.x] + woff[wid] + lane_excl;
    if (i0 + 0 < N_NODES) { rowptr[i0 + 0] = p; cursor[i0 + 0] = p; } p += d0;
    if (i0 + 1 < N_NODES) { rowptr[i0 + 1] = p; cursor[i0 + 1] = p; } p += d1;
    if (i0 + 2 < N_NODES) { rowptr[i0 + 2] = p; cursor[i0 + 2] = p; } p += d2;
    if (i0 + 3 < N_NODES) { rowptr[i0 + 3] = p; cursor[i0 + 3] = p; }
}

__global__ void scatter_kernel(const int* __restrict__ row, const int* __restrict__ col,
                               const float* __restrict__ val, int nnz,
                               int* __restrict__ cursor,
                               int* __restrict__ ccol, float* __restrict__ cval) {
    int e = blockIdx.x * blockDim.x + threadIdx.x;
    if (e >= nnz) return;
    int pos = atomicAdd(&cursor[__ldg(row + e)], 1);
    ccol[pos] = __ldg(col + e);
    cval[pos] = __ldg(val + e);
}

// ================= pull SpMM =================
// layer 1: dst[r] = sum val * emb0[col], emb0 read straight from inputs
__global__ void pull_all_kernel(const float* __restrict__ user_rel,
                                const float* __restrict__ item_rel,
                                const int* __restrict__ rowptr,
                                const int* __restrict__ ccol, const float* __restrict__ cval,
                                float* __restrict__ dst) {
    int w = (blockIdx.x * blockDim.x + threadIdx.x) >> 5;
    int lane = threadIdx.x & 31;
    if (w >= N_NODES) return;
    int s = __ldg(rowptr + w), e = __ldg(rowptr + w + 1);
    float ax = 0.f, ay = 0.f;
    for (int j = s; j < e; j++) {
        int c = __ldg(ccol + j);
        float v = __ldg(cval + j);
        const float* src = (c < N_USER) ? user_rel + (size_t)c * DIM
                                        : item_rel + (size_t)(c - N_USER) * DIM;
        float2 x = *reinterpret_cast<const float2*>(src + lane * 2);
        ax += v * x.x; ay += v * x.y;
    }
    *reinterpret_cast<float2*>(dst + (size_t)w * DIM + lane * 2) = make_float2(ax, ay);
}

// mark flag2 = batch nodes + their neighbors (walk batch CSR rows)
__global__ void mark2_kernel(const int* __restrict__ uid, const int* __restrict__ iid,
                             const int* __restrict__ rowptr, const int* __restrict__ ccol,
                             unsigned char* __restrict__ flag2) {
    int w = (blockIdx.x * blockDim.x + threadIdx.x) >> 5;
    int lane = threadIdx.x & 31;
    if (w >= 2 * BATCH) return;
    int node = (w < BATCH) ? __ldg(uid + w) : N_USER + __ldg(iid + w - BATCH);
    if (lane == 0) flag2[node] = 1;
    int s = __ldg(rowptr + node), e = __ldg(rowptr + node + 1);
    for (int j = s + lane; j < e; j += 32) flag2[__ldg(ccol + j)] = 1;
}

__global__ void node_compact_kernel(const unsigned char* __restrict__ flag2,
                                    int* __restrict__ list, int* __restrict__ count) {
    int n = blockIdx.x * blockDim.x + threadIdx.x;
    bool act = (n < N_NODES) && (flag2[n] != 0);
    unsigned mask = __ballot_sync(0xffffffffu, act);
    int c = __popc(mask);
    int lane = threadIdx.x & 31;
    int base = 0;
    if (lane == 0 && c) base = atomicAdd(count, c);
    base = __shfl_sync(0xffffffffu, base, 0);
    if (act) list[base + __popc(mask & ((1u << lane) - 1))] = n;
}

// layer 2: pull listed rows, src = e1 (full), overwrite dst rows
__global__ void pull_list_kernel(const float* __restrict__ src, float* __restrict__ dst,
                                 const int* __restrict__ rowptr,
                                 const int* __restrict__ ccol, const float* __restrict__ cval,
                                 const int* __restrict__ list, const int* __restrict__ count) {
    int nw = (gridDim.x * blockDim.x) >> 5;
    int lane = threadIdx.x & 31;
    int n = *count;
    for (int w = (blockIdx.x * blockDim.x + threadIdx.x) >> 5; w < n; w += nw) {
        int r = __ldg(list + w);
        int s = __ldg(rowptr + r), e = __ldg(rowptr + r + 1);
        float ax = 0.f, ay = 0.f;
        for (int j = s; j < e; j++) {
            int c = __ldg(ccol + j);
            float v = __ldg(cval + j);
            float2 x = *reinterpret_cast<const float2*>(src + (size_t)c * DIM + lane * 2);
            ax += v * x.x; ay += v * x.y;
        }
        *reinterpret_cast<float2*>(dst + (size_t)r * DIM + lane * 2) = make_float2(ax, ay);
    }
}

// layer 3: pull the 2048 batch rows, src = e2, into compact e3 buffer
__global__ void pull_batch_kernel(const int* __restrict__ uid, const int* __restrict__ iid,
                                  const float* __restrict__ src,
                                  const int* __restrict__ rowptr,
                                  const int* __restrict__ ccol, const float* __restrict__ cval,
                                  float* __restrict__ e3) {
    int w = (blockIdx.x * blockDim.x + threadIdx.x) >> 5;
    int lane = threadIdx.x & 31;
    if (w >= 2 * BATCH) return;
    int node = (w < BATCH) ? __ldg(uid + w) : N_USER + __ldg(iid + w - BATCH);
    int s = __ldg(rowptr + node), e = __ldg(rowptr + node + 1);
    float ax = 0.f, ay = 0.f;
    for (int j = s; j < e; j++) {
        int c = __ldg(ccol + j);
        float v = __ldg(cval + j);
        float2 x = *reinterpret_cast<const float2*>(src + (size_t)c * DIM + lane * 2);
        ax += v * x.x; ay += v * x.y;
    }
    *reinterpret_cast<float2*>(e3 + (size_t)w * DIM + lane * 2) = make_float2(ax, ay);
}

// ---------------- multi-hot row sums --------------------------------------
__global__ void rowsums_kernel(const int* __restrict__ aux, float* __restrict__ sums) {
    int b = blockIdx.x;
    int t = threadIdx.x;
    const int* a = aux + (size_t)b * AUX_LD;
    float s0 = 0.f, s1 = 0.f, s2 = 0.f;
    for (int j = 1 + t;    j < 26;    j += 256) s0 += (float)a[j];
    for (int j = 26 + t;   j < 2212;  j += 256) s1 += (float)a[j];
    for (int j = 2212 + t; j < 10242; j += 256) s2 += (float)a[j];
    __shared__ float sd0[256], sd1[256], sd2[256];
    sd0[t] = s0; sd1[t] = s1; sd2[t] = s2;
    __syncthreads();
    for (int off = 128; off > 0; off >>= 1) {
        if (t < off) { sd0[t] += sd0[t + off]; sd1[t] += sd1[t + off]; sd2[t] += sd2[t + off]; }
        __syncthreads();
    }
    if (t == 0) {
        sums[b * 3 + 0] = sd0[0];
        sums[b * 3 + 1] = sd1[0];
        sums[b * 3 + 2] = sd2[0];
    }
}

// ---------------- multi-hot GEMM: X[:,colOut:colOut+64] += (x@W)/rowsum ----
__global__ __launch_bounds__(256)
void mh_gemm_kernel(const int* __restrict__ aux, int colIn, int K, int tilesPerBlock,
                    const float* __restrict__ W,
                    const float* __restrict__ sums, int sumIdx,
                    float* __restrict__ X, int colOut) {
    __shared__ float xs[32][68];
    __shared__ float ws[32][64];
    int t  = threadIdx.x;
    int tx = t & 15;
    int ty = t >> 4;
    int rowBase = blockIdx.x * 64;
    int kStart = blockIdx.y * tilesPerBlock * 32;
    int kEnd   = min(K, kStart + tilesPerBlock * 32);

    float acc[4][4] = {};
    for (int k0 = kStart; k0 < kEnd; k0 += 32) {
        #pragma unroll
        for (int i = 0; i < 8; i++) {
            int l = t + 256 * i;
            int kk = l & 31, rr = l >> 5;
            int kg = k0 + kk;
            xs[kk][rr] = (kg < K) ? (float)aux[(size_t)(rowBase + rr) * AUX_LD + colIn + kg] : 0.f;
        }
        #pragma unroll
        for (int i = 0; i < 8; i++) {
            int l = t + 256 * i;
            int cc = l & 63, kk = l >> 6;
            int kg = k0 + kk;
            ws[kk][cc] = (kg < K) ? W[(size_t)kg * 64 + cc] : 0.f;
        }
        __syncthreads();
        #pragma unroll
        for (int k = 0; k < 32; k++) {
            float4 wv = *reinterpret_cast<float4*>(&ws[k][tx * 4]);
            float4 av = *reinterpret_cast<float4*>(&xs[k][ty * 4]);
            acc[0][0] += av.x * wv.x; acc[0][1] += av.x * wv.y; acc[0][2] += av.x * wv.z; acc[0][3] += av.x * wv.w;
            acc[1][0] += av.y * wv.x; acc[1][1] += av.y * wv.y; acc[1][2] += av.y * wv.z; acc[1][3] += av.y * wv.w;
            acc[2][0] += av.z * wv.x; acc[2][1] += av.z * wv.y; acc[2][2] += av.z * wv.z; acc[2][3] += av.z * wv.w;
            acc[3][0] += av.w * wv.x; acc[3][1] += av.w * wv.y; acc[3][2] += av.w * wv.z; acc[3][3] += av.w * wv.w;
        }
        __syncthreads();
    }
    #pragma unroll
    for (int r = 0; r < 4; r++) {
        int row = rowBase + ty * 4 + r;
        float rn = 1.0f / sums[row * 3 + sumIdx];
        float4 v = make_float4(acc[r][0] * rn, acc[r][1] * rn, acc[r][2] * rn, acc[r][3] * rn);
        red_add_v4(&X[(size_t)row * XCOLS + colOut + tx * 4], v);
    }
}

// ---------------- dense GEMM (partial sums into pre-zeroed out) -----------
__global__ __launch_bounds__(256)
void fc_gemm_kernel(const float* __restrict__ A, int lda, int K, int tilesPerBlock,
                    const float* __restrict__ W, float* __restrict__ out, int ldo) {
    __shared__ float xs[32][68];
    __shared__ float ws[32][64];
    int t  = threadIdx.x;
    int tx = t & 15;
    int ty = t >> 4;
    int rowBase = blockIdx.x * 64;
    int kStart = blockIdx.y * tilesPerBlock * 32;
    int kEnd   = min(K, kStart + tilesPerBlock * 32);

    float acc[4][4] = {};
    for (int k0 = kStart; k0 < kEnd; k0 += 32) {
        #pragma unroll
        for (int i = 0; i < 8; i++) {
            int l = t + 256 * i;
            int kk = l & 31, rr = l >> 5;
            int kg = k0 + kk;
            xs[kk][rr] = (kg < K) ? A[(size_t)(rowBase + rr) * lda + kg] : 0.f;
        }
        #pragma unroll
        for (int i = 0; i < 8; i++) {
            int l = t + 256 * i;
            int cc = l & 63, kk = l >> 6;
            int kg = k0 + kk;
            ws[kk][cc] = (kg < K) ? W[(size_t)kg * 64 + cc] : 0.f;
        }
        __syncthreads();
        #pragma unroll
        for (int k = 0; k < 32; k++) {
            float4 wv = *reinterpret_cast<float4*>(&ws[k][tx * 4]);
            float4 av = *reinterpret_cast<float4*>(&xs[k][ty * 4]);
            acc[0][0] += av.x * wv.x; acc[0][1] += av.x * wv.y; acc[0][2] += av.x * wv.z; acc[0][3] += av.x * wv.w;
            acc[1][0] += av.y * wv.x; acc[1][1] += av.y * wv.y; acc[1][2] += av.y * wv.z; acc[1][3] += av.y * wv.w;
            acc[2][0] += av.z * wv.x; acc[2][1] += av.z * wv.y; acc[2][2] += av.z * wv.z; acc[2][3] += av.z * wv.w;
            acc[3][0] += av.w * wv.x; acc[3][1] += av.w * wv.y; acc[3][2] += av.w * wv.z; acc[3][3] += av.w * wv.w;
        }
        __syncthreads();
    }
    #pragma unroll
    for (int r = 0; r < 4; r++) {
        int row = rowBase + ty * 4 + r;
        float4 v = make_float4(acc[r][0], acc[r][1], acc[r][2], acc[r][3]);
        red_add_v4(&out[(size_t)row * ldo + tx * 4], v);
    }
}

__global__ void bias_act_kernel(float* __restrict__ h, const float* __restrict__ b, int n) {
    int i = blockIdx.x * blockDim.x + threadIdx.x;
    if (i >= n) return;
    float v = h[i] + b[i & 63];
    h[i] = v > 0.f ? v : 0.f;
}

// ---------------- gathers: tables + LightGCN sum (emb0+e1+e2+e3)/4 --------
__global__ void gather_kernel(const int* __restrict__ aux,
                              const int* __restrict__ uid, const int* __restrict__ iid,
                              const float* __restrict__ rate_tab,
                              const float* __restrict__ gender_tab,
                              const float* __restrict__ age_tab,
                              const float* __restrict__ occ_tab,
                              const float* __restrict__ area_tab,
                              const float* __restrict__ user_rel,
                              const float* __restrict__ item_rel,
                              const float* __restrict__ e1,
                              const float* __restrict__ e2,
                              const float* __restrict__ e3,
                              float* __restrict__ X) {
    int b = blockIdx.x;
    int d = threadIdx.x;   // 64
    const int* a = aux + (size_t)b * AUX_LD;
    float* xr = X + (size_t)b * XCOLS;
    xr[0   + d] = rate_tab  [(size_t)a[0]     * 64 + d];
    xr[256 + d] = gender_tab[(size_t)a[10242] * 64 + d];
    xr[320 + d] = age_tab   [(size_t)a[10243] * 64 + d];
    xr[384 + d] = occ_tab   [(size_t)a[10244] * 64 + d];
    xr[448 + d] = area_tab  [(size_t)a[10245] * 64 + d];
    int u  = uid[b];
    int it = iid[b];
    size_t un  = (size_t)u * 64 + d;
    size_t in_ = ((size_t)N_USER + it) * 64 + d;
    xr[512 + d] = 0.25f * (user_rel[un] + e1[un] + e2[un] + e3[(size_t)b * 64 + d]);
    xr[576 + d] = 0.25f * (item_rel[(size_t)it * 64 + d] + e1[in_] + e2[in_]
                           + e3[(size_t)(BATCH + b) * 64 + d]);
}

// ---------------- final dot -----------------------------------------------
__global__ void out_kernel(const float* __restrict__ H2, const float* __restrict__ w,
                           const float* __restrict__ ob, float* __restrict__ out) {
    int b = blockIdx.x;
    int t = threadIdx.x;   // 64
    __shared__ float s[64];
    s[t] = H2[(size_t)b * 64 + t] * w[t];
    __syncthreads();
    for (int off = 32; off > 0; off >>= 1) {
        if (t < off) s[t] += s[t + off];
        __syncthreads();
    }
    if (t == 0) out[b] = s[0] + ob[0];
}

// ---------------- launch ---------------------------------------------------
extern "C" void kernel_launch(void* const* d_in, const int* in_sizes, int n_in,
                              void* d_out, int out_size) {
    const int*   aux       = (const int*)  d_in[0];
    const int*   user_ids  = (const int*)  d_in[1];
    const int*   item_ids  = (const int*)  d_in[2];
    const int*   grow      = (const int*)  d_in[3];
    const int*   gcol      = (const int*)  d_in[4];
    const float* gval      = (const float*)d_in[5];
    const float* rate_tab  = (const float*)d_in[6];
    const float* genre_W   = (const float*)d_in[7];
    const float* director_W= (const float*)d_in[8];
    const float* actor_W   = (const float*)d_in[9];
    const float* gender_tab= (const float*)d_in[10];
    const float* age_tab   = (const float*)d_in[11];
    const float* occ_tab   = (const float*)d_in[12];
    const float* area_tab  = (const float*)d_in[13];
    const float* user_rel  = (const float*)d_in[14];
    const float* item_rel  = (const float*)d_in[15];
    const float* fc1_W     = (const float*)d_in[16];
    const float* fc1_b     = (const float*)d_in[17];
    const float* fc2_W     = (const float*)d_in[18];
    const float* fc2_b     = (const float*)d_in[19];
    const float* out_W     = (const float*)d_in[20];
    const float* out_b     = (const float*)d_in[21];
    int nnz = in_sizes[3];

    float *embB, *embC, *e3, *X, *H1, *H2, *sums;
    unsigned char* flag2;
    int *nlist2, *cnt, *deg, *rowptr, *cursor, *ccol, *bsum, *boffs;
    float* cval;
    cudaGetSymbolAddress((void**)&embB,  g_embB);
    cudaGetSymbolAddress((void**)&embC,  g_embC);
    cudaGetSymbolAddress((void**)&e3,    g_e3);
    cudaGetSymbolAddress((void**)&X,     g_X);
    cudaGetSymbolAddress((void**)&H1,    g_H1);
    cudaGetSymbolAddress((void**)&H2,    g_H2);
    cudaGetSymbolAddress((void**)&sums,  g_sums);
    cudaGetSymbolAddress((void**)&flag2, g_flag2);
    cudaGetSymbolAddress((void**)&nlist2,g_nlist2);
    cudaGetSymbolAddress((void**)&cnt,   g_cnt);
    cudaGetSymbolAddress((void**)&deg,   g_deg);
    cudaGetSymbolAddress((void**)&rowptr,g_rowptr);
    cudaGetSymbolAddress((void**)&cursor,g_cursor);
    cudaGetSymbolAddress((void**)&ccol,  g_csr_col);
    cudaGetSymbolAddress((void**)&cval,  g_csr_val);
    cudaGetSymbolAddress((void**)&bsum,  g_bsum);
    cudaGetSymbolAddress((void**)&boffs, g_boffs);

    const int EB = (nnz + 255) / 256;
    const int NB = (N_NODES + 1023) / 1024;   // 176

    // --- multi-hot path (independent of GCN) ---
    rowsums_kernel<<<BATCH, 256>>>(aux, sums);
    cudaMemsetAsync(X, 0, (size_t)BATCH * XCOLS * sizeof(float));
    mh_gemm_kernel<<<dim3(16, 1),  256>>>(aux, 1,    25,   1, genre_W,    sums, 0, X, 64);
    mh_gemm_kernel<<<dim3(16, 14), 256>>>(aux, 26,   2186, 5, director_W, sums, 1, X, 128);
    mh_gemm_kernel<<<dim3(16, 28), 256>>>(aux, 2212, 8030, 9, actor_W,    sums, 2, X, 192);

    // --- CSR build ---
    cudaMemsetAsync(deg, 0, N_NODES * sizeof(int));
    cudaMemsetAsync(flag2, 0, N_NODES);
    cudaMemsetAsync(cnt, 0, 4 * sizeof(int));
    hist_kernel<<<EB, 256>>>(grow, nnz, deg);
    bsum_kernel<<<NB, 256>>>(deg, bsum);
    bscan_kernel<<<1, 256>>>(bsum, boffs, NB, nnz, rowptr);
    scan_kernel<<<NB, 256>>>(deg, boffs, rowptr, cursor);
    scatter_kernel<<<EB, 256>>>(grow, gcol, gval, nnz, cursor, ccol, cval);

    // --- flag2 = batch ∪ neighbors(batch); compact node list ---
    mark2_kernel<<<(2 * BATCH * 32 + 255) / 256, 256>>>(user_ids, item_ids, rowptr, ccol, flag2);
    node_compact_kernel<<<(N_NODES + 255) / 256, 256>>>(flag2, nlist2, cnt + 0);

    // --- LightGCN: 3 pull layers ---
    // layer 1 (full): e1 = P @ emb0 (emb0 read from user_rel/item_rel)
    pull_all_kernel<<<(N_NODES * 32 + 255) / 256, 256>>>(user_rel, item_rel,
                                                         rowptr, ccol, cval, embB);
    // layer 2 (flag2 rows): e2 = P @ e1
    pull_list_kernel<<<2048, 256>>>(embB, embC, rowptr, ccol, cval, nlist2, cnt + 0);
    // layer 3 (batch rows): e3 = P @ e2
    pull_batch_kernel<<<(2 * BATCH * 32 + 255) / 256, 256>>>(user_ids, item_ids, embC,
                                                             rowptr, ccol, cval, e3);

    // --- assemble X ---
    gather_kernel<<<BATCH, 64>>>(aux, user_ids, item_ids, rate_tab, gender_tab,
                                 age_tab, occ_tab, area_tab,
                                 user_rel, item_rel, embB, embC, e3, X);

    // --- MLP ---
    cudaMemsetAsync(H1, 0, (size_t)BATCH * DIM * sizeof(float));
    fc_gemm_kernel<<<dim3(16, 20), 256>>>(X, XCOLS, XCOLS, 1, fc1_W, H1, 64);
    bias_act_kernel<<<(BATCH * DIM + 255) / 256, 256>>>(H1, fc1_b, BATCH * DIM);

    cudaMemsetAsync(H2, 0, (size_t)BATCH * DIM * sizeof(float));
    fc_gemm_kernel<<<dim3(16, 2), 256>>>(H1, 64, 64, 1, fc2_W, H2, 64);
    bias_act_kernel<<<(BATCH * DIM + 255) / 256, 256>>>(H2, fc2_b, BATCH * DIM);

    out_kernel<<<BATCH, 64>>>(H2, out_W, out_b, (float*)d_out);
}

// round 12
// speedup vs baseline: 2.9613x; 1.0729x over previous
#include <cuda_runtime.h>
#include <cstdint>

#define N_USER   150000
#define M_ITEM   30000
#define N_NODES  180000
#define DIM      64
#define BATCH    1024
#define AUX_LD   10246
#define XCOLS    640
#define MAXE     1300000

// ---------------- scratch (static device memory; no allocs allowed) --------
__device__ float g_embB[(size_t)N_NODES * DIM];   // e1 (full)
__device__ float g_embC[(size_t)N_NODES * DIM];   // e2 (valid at flag2 rows)
__device__ float g_e3  [2 * BATCH * DIM];         // e3 at batch positions
__device__ float g_X   [BATCH * XCOLS];
__device__ float g_H1  [BATCH * DIM];
__device__ float g_H2  [BATCH * DIM];
__device__ float g_sums[BATCH * 3];
__device__ unsigned char g_flag2[N_NODES];
__device__ int   g_nlist2[N_NODES];
__device__ int   g_cnt[4];
// CSR
__device__ int   g_deg   [N_NODES];
__device__ int   g_rowptr[N_NODES + 1];
__device__ int   g_cursor[N_NODES];
__device__ int   g_csr_col[MAXE];
__device__ float g_csr_val[MAXE];
__device__ int   g_bsum [256];
__device__ int   g_boffs[256];

// vectorized no-return global reductions (sm_90+)
__device__ __forceinline__ void red_add_v4(float* p, float4 v) {
    asm volatile("red.global.add.v4.f32 [%0], {%1,%2,%3,%4};"
                 :: "l"(p), "f"(v.x), "f"(v.y), "f"(v.z), "f"(v.w) : "memory");
}
__device__ __forceinline__ void red_add_v2(float* p, float a, float b) {
    asm volatile("red.global.add.v2.f32 [%0], {%1,%2};"
                 :: "l"(p), "f"(a), "f"(b) : "memory");
}
__device__ __forceinline__ unsigned f2tf32(float f) {
    unsigned u;
    asm("cvt.rna.tf32.f32 %0, %1;" : "=r"(u) : "f"(f));
    return u;
}

// ================= CSR build =================
__global__ void hist_kernel(const int* __restrict__ row, int nnz, int* __restrict__ deg) {
    int e = blockIdx.x * blockDim.x + threadIdx.x;
    if (e < nnz) atomicAdd(&deg[__ldg(row + e)], 1);
}

__global__ void bsum_kernel(const int* __restrict__ deg, int* __restrict__ bsum) {
    int b = blockIdx.x, t = threadIdx.x;
    int i0 = b * 1024 + t * 4;
    int s = 0;
    #pragma unroll
    for (int k = 0; k < 4; k++) {
        int i = i0 + k;
        if (i < N_NODES) s += deg[i];
    }
    __shared__ int sd[256];
    sd[t] = s;
    __syncthreads();
    for (int off = 128; off > 0; off >>= 1) {
        if (t < off) sd[t] += sd[t + off];
        __syncthreads();
    }
    if (t == 0) bsum[b] = sd[0];
}

__global__ void bscan_kernel(const int* __restrict__ bsum, int* __restrict__ boffs,
                             int nb, int nnz, int* __restrict__ rowptr) {
    int t = threadIdx.x;
    __shared__ int s[256];
    int orig = (t < nb) ? bsum[t] : 0;
    s[t] = orig;
    __syncthreads();
    for (int off = 1; off < 256; off <<= 1) {
        int v = (t >= off) ? s[t - off] : 0;
        __syncthreads();
        s[t] += v;
        __syncthreads();
    }
    boffs[t] = s[t] - orig;
    if (t == 0) rowptr[N_NODES] = nnz;
}

__global__ void scan_kernel(const int* __restrict__ deg, const int* __restrict__ boffs,
                            int* __restrict__ rowptr, int* __restrict__ cursor) {
    int t = threadIdx.x;
    int lane = t & 31, wid = t >> 5;
    int i0 = blockIdx.x * 1024 + t * 4;
    int d0 = (i0 + 0 < N_NODES) ? deg[i0 + 0] : 0;
    int d1 = (i0 + 1 < N_NODES) ? deg[i0 + 1] : 0;
    int d2 = (i0 + 2 < N_NODES) ? deg[i0 + 2] : 0;
    int d3 = (i0 + 3 < N_NODES) ? deg[i0 + 3] : 0;
    int ts = d0 + d1 + d2 + d3;
    int x = ts;
    #pragma unroll
    for (int off = 1; off < 32; off <<= 1) {
        int y = __shfl_up_sync(0xffffffffu, x, off);
        if (lane >= off) x += y;
    }
    int lane_excl = x - ts;
    __shared__ int wtot[8], woff[8];
    if (lane == 31) wtot[wid] = x;
    __syncthreads();
    if (t == 0) {
        int r = 0;
        #pragma unroll
        for (int k = 0; k < 8; k++) { woff[k] = r; r += wtot[k]; }
    }
    __syncthreads();
    int p = boffs[blockIdx.x] + woff[wid] + lane_excl;
    if (i0 + 0 < N_NODES) { rowptr[i0 + 0] = p; cursor[i0 + 0] = p; } p += d0;
    if (i0 + 1 < N_NODES) { rowptr[i0 + 1] = p; cursor[i0 + 1] = p; } p += d1;
    if (i0 + 2 < N_NODES) { rowptr[i0 + 2] = p; cursor[i0 + 2] = p; } p += d2;
    if (i0 + 3 < N_NODES) { rowptr[i0 + 3] = p; cursor[i0 + 3] = p; }
}

__global__ void scatter_kernel(const int* __restrict__ row, const int* __restrict__ col,
                               const float* __restrict__ val, int nnz,
                               int* __restrict__ cursor,
                               int* __restrict__ ccol, float* __restrict__ cval) {
    int e = blockIdx.x * blockDim.x + threadIdx.x;
    if (e >= nnz) return;
    int pos = atomicAdd(&cursor[__ldg(row + e)], 1);
    ccol[pos] = __ldg(col + e);
    cval[pos] = __ldg(val + e);
}

// ================= pull SpMM =================
__global__ void pull_all_kernel(const float* __restrict__ user_rel,
                                const float* __restrict__ item_rel,
                                const int* __restrict__ rowptr,
                                const int* __restrict__ ccol, const float* __restrict__ cval,
                                float* __restrict__ dst) {
    int w = (blockIdx.x * blockDim.x + threadIdx.x) >> 5;
    int lane = threadIdx.x & 31;
    if (w >= N_NODES) return;
    int s = __ldg(rowptr + w), e = __ldg(rowptr + w + 1);
    float ax = 0.f, ay = 0.f;
    for (int j = s; j < e; j++) {
        int c = __ldg(ccol + j);
        float v = __ldg(cval + j);
        const float* src = (c < N_USER) ? user_rel + (size_t)c * DIM
                                        : item_rel + (size_t)(c - N_USER) * DIM;
        float2 x = *reinterpret_cast<const float2*>(src + lane * 2);
        ax += v * x.x; ay += v * x.y;
    }
    *reinterpret_cast<float2*>(dst + (size_t)w * DIM + lane * 2) = make_float2(ax, ay);
}

__global__ void mark2_kernel(const int* __restrict__ uid, const int* __restrict__ iid,
                             const int* __restrict__ rowptr, const int* __restrict__ ccol,
                             unsigned char* __restrict__ flag2) {
    int w = (blockIdx.x * blockDim.x + threadIdx.x) >> 5;
    int lane = threadIdx.x & 31;
    if (w >= 2 * BATCH) return;
    int node = (w < BATCH) ? __ldg(uid + w) : N_USER + __ldg(iid + w - BATCH);
    if (lane == 0) flag2[node] = 1;
    int s = __ldg(rowptr + node), e = __ldg(rowptr + node + 1);
    for (int j = s + lane; j < e; j += 32) flag2[__ldg(ccol + j)] = 1;
}

__global__ void node_compact_kernel(const unsigned char* __restrict__ flag2,
                                    int* __restrict__ list, int* __restrict__ count) {
    int n = blockIdx.x * blockDim.x + threadIdx.x;
    bool act = (n < N_NODES) && (flag2[n] != 0);
    unsigned mask = __ballot_sync(0xffffffffu, act);
    int c = __popc(mask);
    int lane = threadIdx.x & 31;
    int base = 0;
    if (lane == 0 && c) base = atomicAdd(count, c);
    base = __shfl_sync(0xffffffffu, base, 0);
    if (act) list[base + __popc(mask & ((1u << lane) - 1))] = n;
}

__global__ void pull_list_kernel(const float* __restrict__ src, float* __restrict__ dst,
                                 const int* __restrict__ rowptr,
                                 const int* __restrict__ ccol, const float* __restrict__ cval,
                                 const int* __restrict__ list, const int* __restrict__ count) {
    int nw = (gridDim.x * blockDim.x) >> 5;
    int lane = threadIdx.x & 31;
    int n = *count;
    for (int w = (blockIdx.x * blockDim.x + threadIdx.x) >> 5; w < n; w += nw) {
        int r = __ldg(list + w);
        int s = __ldg(rowptr + r), e = __ldg(rowptr + r + 1);
        float ax = 0.f, ay = 0.f;
        for (int j = s; j < e; j++) {
            int c = __ldg(ccol + j);
            float v = __ldg(cval + j);
            float2 x = *reinterpret_cast<const float2*>(src + (size_t)c * DIM + lane * 2);
            ax += v * x.x; ay += v * x.y;
        }
        *reinterpret_cast<float2*>(dst + (size_t)r * DIM + lane * 2) = make_float2(ax, ay);
    }
}

__global__ void pull_batch_kernel(const int* __restrict__ uid, const int* __restrict__ iid,
                                  const float* __restrict__ src,
                                  const int* __restrict__ rowptr,
                                  const int* __restrict__ ccol, const float* __restrict__ cval,
                                  float* __restrict__ e3) {
    int w = (blockIdx.x * blockDim.x + threadIdx.x) >> 5;
    int lane = threadIdx.x & 31;
    if (w >= 2 * BATCH) return;
    int node = (w < BATCH) ? __ldg(uid + w) : N_USER + __ldg(iid + w - BATCH);
    int s = __ldg(rowptr + node), e = __ldg(rowptr + node + 1);
    float ax = 0.f, ay = 0.f;
    for (int j = s; j < e; j++) {
        int c = __ldg(ccol + j);
        float v = __ldg(cval + j);
        float2 x = *reinterpret_cast<const float2*>(src + (size_t)c * DIM + lane * 2);
        ax += v * x.x; ay += v * x.y;
    }
    *reinterpret_cast<float2*>(e3 + (size_t)w * DIM + lane * 2) = make_float2(ax, ay);
}

// ---------------- multi-hot row sums --------------------------------------
__global__ void rowsums_kernel(const int* __restrict__ aux, float* __restrict__ sums) {
    int b = blockIdx.x;
    int t = threadIdx.x;
    const int* a = aux + (size_t)b * AUX_LD;
    float s0 = 0.f, s1 = 0.f, s2 = 0.f;
    for (int j = 1 + t;    j < 26;    j += 256) s0 += (float)a[j];
    for (int j = 26 + t;   j < 2212;  j += 256) s1 += (float)a[j];
    for (int j = 2212 + t; j < 10242; j += 256) s2 += (float)a[j];
    __shared__ float sd0[256], sd1[256], sd2[256];
    sd0[t] = s0; sd1[t] = s1; sd2[t] = s2;
    __syncthreads();
    for (int off = 128; off > 0; off >>= 1) {
        if (t < off) { sd0[t] += sd0[t + off]; sd1[t] += sd1[t + off]; sd2[t] += sd2[t + off]; }
        __syncthreads();
    }
    if (t == 0) {
        sums[b * 3 + 0] = sd0[0];
        sums[b * 3 + 1] = sd1[0];
        sums[b * 3 + 2] = sd2[0];
    }
}

// ------- multi-hot GEMM via tf32 tensor cores: X += (A@W)/rowsum ----------
// Block: 64 rows x 64 cols, 8 warps of 16x32 (4 m16n8k8 n-tiles), K-split.
// A in {0,1} (exact in tf32); W rounded with cvt.rna.tf32.
__global__ __launch_bounds__(256)
void mh_gemm_tc_kernel(const int* __restrict__ aux, int colIn, int K, int tilesPerBlock,
                       const float* __restrict__ W,
                       const float* __restrict__ sums, int sumIdx,
                       float* __restrict__ X, int colOut) {
    __shared__ unsigned xs[64][36];   // A tile, [row][k]
    __shared__ unsigned ws[32][72];   // W tile, [k][n]
    int t = threadIdx.x;
    int wrp = t >> 5, lane = t & 31;
    int wr = wrp >> 1;                // row group 0..3  (rows 16*wr)
    int wc = wrp & 1;                 // col half 0..1   (cols 32*wc)
    int rowBase = blockIdx.x * 64;
    int kStart = blockIdx.y * tilesPerBlock * 32;
    int kEnd   = min(K, kStart + tilesPerBlock * 32);

    float acc[4][4] = {};             // [ntile][c0..c3]

    for (int k0 = kStart; k0 < kEnd; k0 += 32) {
        #pragma unroll
        for (int i = 0; i < 8; i++) {
            int l = t + 256 * i;
            int kk = l & 31, rr = l >> 5;
            int kg = k0 + kk;
            float a = (kg < K) ? (float)aux[(size_t)(rowBase + rr) * AUX_LD + colIn + kg] : 0.f;
            xs[rr][kk] = __float_as_uint(a);   // 0/1 exact in tf32
        }
        #pragma unroll
        for (int i = 0; i < 8; i++) {
            int l = t + 256 * i;
            int cc = l & 63, kk = l >> 6;
            int kg = k0 + kk;
            ws[kk][cc] = (kg < K) ? f2tf32(W[(size_t)kg * 64 + cc]) : 0u;
        }
        __syncthreads();
        int ar0 = wr * 16 + (lane >> 2);
        int kc  = lane & 3;
        #pragma unroll
        for (int ks = 0; ks < 32; ks += 8) {
            unsigned a0 = xs[ar0    ][ks + kc];
            unsigned a1 = xs[ar0 + 8][ks + kc];
            unsigned a2 = xs[ar0    ][ks + kc + 4];
            unsigned a3 = xs[ar0 + 8][ks + kc + 4];
            #pragma unroll
            for (int nt = 0; nt < 4; nt++) {
                int n = wc * 32 + nt * 8 + (lane >> 2);
                unsigned b0 = ws[ks + kc    ][n];
                unsigned b1 = ws[ks + kc + 4][n];
                asm volatile(
                    "mma.sync.aligned.m16n8k8.row.col.f32.tf32.tf32.f32 "
                    "{%0,%1,%2,%3}, {%4,%5,%6,%7}, {%8,%9}, {%0,%1,%2,%3};"
                    : "+f"(acc[nt][0]), "+f"(acc[nt][1]), "+f"(acc[nt][2]), "+f"(acc[nt][3])
                    : "r"(a0), "r"(a1), "r"(a2), "r"(a3), "r"(b0), "r"(b1));
            }
        }
        __syncthreads();
    }

    int r0 = rowBase + wr * 16 + (lane >> 2);
    int r1 = r0 + 8;
    float rn0 = 1.0f / sums[r0 * 3 + sumIdx];
    float rn1 = 1.0f / sums[r1 * 3 + sumIdx];
    #pragma unroll
    for (int nt = 0; nt < 4; nt++) {
        int c = colOut + wc * 32 + nt * 8 + 2 * (lane & 3);
        red_add_v2(&X[(size_t)r0 * XCOLS + c], acc[nt][0] * rn0, acc[nt][1] * rn0);
        red_add_v2(&X[(size_t)r1 * XCOLS + c], acc[nt][2] * rn1, acc[nt][3] * rn1);
    }
}

// ---------------- dense GEMM (fp32; partial sums into pre-zeroed out) -----
__global__ __launch_bounds__(256)
void fc_gemm_kernel(const float* __restrict__ A, int lda, int K, int tilesPerBlock,
                    const float* __restrict__ W, float* __restrict__ out, int ldo) {
    __shared__ float xs[32][68];
    __shared__ float ws[32][64];
    int t  = threadIdx.x;
    int tx = t & 15;
    int ty = t >> 4;
    int rowBase = blockIdx.x * 64;
    int kStart = blockIdx.y * tilesPerBlock * 32;
    int kEnd   = min(K, kStart + tilesPerBlock * 32);

    float acc[4][4] = {};
    for (int k0 = kStart; k0 < kEnd; k0 += 32) {
        #pragma unroll
        for (int i = 0; i < 8; i++) {
            int l = t + 256 * i;
            int kk = l & 31, rr = l >> 5;
            int kg = k0 + kk;
            xs[kk][rr] = (kg < K) ? A[(size_t)(rowBase + rr) * lda + kg] : 0.f;
        }
        #pragma unroll
        for (int i = 0; i < 8; i++) {
            int l = t + 256 * i;
            int cc = l & 63, kk = l >> 6;
            int kg = k0 + kk;
            ws[kk][cc] = (kg < K) ? W[(size_t)kg * 64 + cc] : 0.f;
        }
        __syncthreads();
        #pragma unroll
        for (int k = 0; k < 32; k++) {
            float4 wv = *reinterpret_cast<float4*>(&ws[k][tx * 4]);
            float4 av = *reinterpret_cast<float4*>(&xs[k][ty * 4]);
            acc[0][0] += av.x * wv.x; acc[0][1] += av.x * wv.y; acc[0][2] += av.x * wv.z; acc[0][3] += av.x * wv.w;
            acc[1][0] += av.y * wv.x; acc[1][1] += av.y * wv.y; acc[1][2] += av.y * wv.z; acc[1][3] += av.y * wv.w;
            acc[2][0] += av.z * wv.x; acc[2][1] += av.z * wv.y; acc[2][2] += av.z * wv.z; acc[2][3] += av.z * wv.w;
            acc[3][0] += av.w * wv.x; acc[3][1] += av.w * wv.y; acc[3][2] += av.w * wv.z; acc[3][3] += av.w * wv.w;
        }
        __syncthreads();
    }
    #pragma unroll
    for (int r = 0; r < 4; r++) {
        int row = rowBase + ty * 4 + r;
        float4 v = make_float4(acc[r][0], acc[r][1], acc[r][2], acc[r][3]);
        red_add_v4(&out[(size_t)row * ldo + tx * 4], v);
    }
}

__global__ void bias_act_kernel(float* __restrict__ h, const float* __restrict__ b, int n) {
    int i = blockIdx.x * blockDim.x + threadIdx.x;
    if (i >= n) return;
    float v = h[i] + b[i & 63];
    h[i] = v > 0.f ? v : 0.f;
}

// ---------------- gathers: tables + LightGCN sum (emb0+e1+e2+e3)/4 --------
__global__ void gather_kernel(const int* __restrict__ aux,
                              const int* __restrict__ uid, const int* __restrict__ iid,
                              const float* __restrict__ rate_tab,
                              const float* __restrict__ gender_tab,
                              const float* __restrict__ age_tab,
                              const float* __restrict__ occ_tab,
                              const float* __restrict__ area_tab,
                              const float* __restrict__ user_rel,
                              const float* __restrict__ item_rel,
                              const float* __restrict__ e1,
                              const float* __restrict__ e2,
                              const float* __restrict__ e3,
                              float* __restrict__ X) {
    int b = blockIdx.x;
    int d = threadIdx.x;   // 64
    const int* a = aux + (size_t)b * AUX_LD;
    float* xr = X + (size_t)b * XCOLS;
    xr[0   + d] = rate_tab  [(size_t)a[0]     * 64 + d];
    xr[256 + d] = gender_tab[(size_t)a[10242] * 64 + d];
    xr[320 + d] = age_tab   [(size_t)a[10243] * 64 + d];
    xr[384 + d] = occ_tab   [(size_t)a[10244] * 64 + d];
    xr[448 + d] = area_tab  [(size_t)a[10245] * 64 + d];
    int u  = uid[b];
    int it = iid[b];
    size_t un  = (size_t)u * 64 + d;
    size_t in_ = ((size_t)N_USER + it) * 64 + d;
    xr[512 + d] = 0.25f * (user_rel[un] + e1[un] + e2[un] + e3[(size_t)b * 64 + d]);
    xr[576 + d] = 0.25f * (item_rel[(size_t)it * 64 + d] + e1[in_] + e2[in_]
                           + e3[(size_t)(BATCH + b) * 64 + d]);
}

// ---------------- final dot -----------------------------------------------
__global__ void out_kernel(const float* __restrict__ H2, const float* __restrict__ w,
                           const float* __restrict__ ob, float* __restrict__ out) {
    int b = blockIdx.x;
    int t = threadIdx.x;   // 64
    __shared__ float s[64];
    s[t] = H2[(size_t)b * 64 + t] * w[t];
    __syncthreads();
    for (int off = 32; off > 0; off >>= 1) {
        if (t < off) s[t] += s[t + off];
        __syncthreads();
    }
    if (t == 0) out[b] = s[0] + ob[0];
}

// ---------------- launch ---------------------------------------------------
extern "C" void kernel_launch(void* const* d_in, const int* in_sizes, int n_in,
                              void* d_out, int out_size) {
    const int*   aux       = (const int*)  d_in[0];
    const int*   user_ids  = (const int*)  d_in[1];
    const int*   item_ids  = (const int*)  d_in[2];
    const int*   grow      = (const int*)  d_in[3];
    const int*   gcol      = (const int*)  d_in[4];
    const float* gval      = (const float*)d_in[5];
    const float* rate_tab  = (const float*)d_in[6];
    const float* genre_W   = (const float*)d_in[7];
    const float* director_W= (const float*)d_in[8];
    const float* actor_W   = (const float*)d_in[9];
    const float* gender_tab= (const float*)d_in[10];
    const float* age_tab   = (const float*)d_in[11];
    const float* occ_tab   = (const float*)d_in[12];
    const float* area_tab  = (const float*)d_in[13];
    const float* user_rel  = (const float*)d_in[14];
    const float* item_rel  = (const float*)d_in[15];
    const float* fc1_W     = (const float*)d_in[16];
    const float* fc1_b     = (const float*)d_in[17];
    const float* fc2_W     = (const float*)d_in[18];
    const float* fc2_b     = (const float*)d_in[19];
    const float* out_W     = (const float*)d_in[20];
    const float* out_b     = (const float*)d_in[21];
    int nnz = in_sizes[3];

    float *embB, *embC, *e3, *X, *H1, *H2, *sums;
    unsigned char* flag2;
    int *nlist2, *cnt, *deg, *rowptr, *cursor, *ccol, *bsum, *boffs;
    float* cval;
    cudaGetSymbolAddress((void**)&embB,  g_embB);
    cudaGetSymbolAddress((void**)&embC,  g_embC);
    cudaGetSymbolAddress((void**)&e3,    g_e3);
    cudaGetSymbolAddress((void**)&X,     g_X);
    cudaGetSymbolAddress((void**)&H1,    g_H1);
    cudaGetSymbolAddress((void**)&H2,    g_H2);
    cudaGetSymbolAddress((void**)&sums,  g_sums);
    cudaGetSymbolAddress((void**)&flag2, g_flag2);
    cudaGetSymbolAddress((void**)&nlist2,g_nlist2);
    cudaGetSymbolAddress((void**)&cnt,   g_cnt);
    cudaGetSymbolAddress((void**)&deg,   g_deg);
    cudaGetSymbolAddress((void**)&rowptr,g_rowptr);
    cudaGetSymbolAddress((void**)&cursor,g_cursor);
    cudaGetSymbolAddress((void**)&ccol,  g_csr_col);
    cudaGetSymbolAddress((void**)&cval,  g_csr_val);
    cudaGetSymbolAddress((void**)&bsum,  g_bsum);
    cudaGetSymbolAddress((void**)&boffs, g_boffs);

    const int EB = (nnz + 255) / 256;
    const int NB = (N_NODES + 1023) / 1024;   // 176

    // --- multi-hot path (tf32 tensor cores; independent of GCN) ---
    rowsums_kernel<<<BATCH, 256>>>(aux, sums);
    cudaMemsetAsync(X, 0, (size_t)BATCH * XCOLS * sizeof(float));
    mh_gemm_tc_kernel<<<dim3(16, 1),  256>>>(aux, 1,    25,   1, genre_W,    sums, 0, X, 64);
    mh_gemm_tc_kernel<<<dim3(16, 14), 256>>>(aux, 26,   2186, 5, director_W, sums, 1, X, 128);
    mh_gemm_tc_kernel<<<dim3(16, 28), 256>>>(aux, 2212, 8030, 9, actor_W,    sums, 2, X, 192);

    // --- CSR build ---
    cudaMemsetAsync(deg, 0, N_NODES * sizeof(int));
    cudaMemsetAsync(flag2, 0, N_NODES);
    cudaMemsetAsync(cnt, 0, 4 * sizeof(int));
    hist_kernel<<<EB, 256>>>(grow, nnz, deg);
    bsum_kernel<<<NB, 256>>>(deg, bsum);
    bscan_kernel<<<1, 256>>>(bsum, boffs, NB, nnz, rowptr);
    scan_kernel<<<NB, 256>>>(deg, boffs, rowptr, cursor);
    scatter_kernel<<<EB, 256>>>(grow, gcol, gval, nnz, cursor, ccol, cval);

    // --- flag2 = batch ∪ neighbors(batch); compact node list ---
    mark2_kernel<<<(2 * BATCH * 32 + 255) / 256, 256>>>(user_ids, item_ids, rowptr, ccol, flag2);
    node_compact_kernel<<<(N_NODES + 255) / 256, 256>>>(flag2, nlist2, cnt + 0);

    // --- LightGCN: 3 pull layers ---
    pull_all_kernel<<<(N_NODES * 32 + 255) / 256, 256>>>(user_rel, item_rel,
                                                         rowptr, ccol, cval, embB);
    pull_list_kernel<<<2048, 256>>>(embB, embC, rowptr, ccol, cval, nlist2, cnt + 0);
    pull_batch_kernel<<<(2 * BATCH * 32 + 255) / 256, 256>>>(user_ids, item_ids, embC,
                                                             rowptr, ccol, cval, e3);

    // --- assemble X ---
    gather_kernel<<<BATCH, 64>>>(aux, user_ids, item_ids, rate_tab, gender_tab,
                                 age_tab, occ_tab, area_tab,
                                 user_rel, item_rel, embB, embC, e3, X);

    // --- MLP ---
    cudaMemsetAsync(H1, 0, (size_t)BATCH * DIM * sizeof(float));
    fc_gemm_kernel<<<dim3(16, 20), 256>>>(X, XCOLS, XCOLS, 1, fc1_W, H1, 64);
    bias_act_kernel<<<(BATCH * DIM + 255) / 256, 256>>>(H1, fc1_b, BATCH * DIM);

    cudaMemsetAsync(H2, 0, (size_t)BATCH * DIM * sizeof(float));
    fc_gemm_kernel<<<dim3(16, 2), 256>>>(H1, 64, 64, 1, fc2_W, H2, 64);
    bias_act_kernel<<<(BATCH * DIM + 255) / 256, 256>>>(H2, fc2_b, BATCH * DIM);

    out_kernel<<<BATCH, 64>>>(H2, out_W, out_b, (float*)d_out);
}